// round 14
// baseline (speedup 1.0000x reference)
#include <cuda_runtime.h>
#include <math.h>

#define NFFT   4096
#define NHALF  2048
#define NSPEC  2049
#define CCH    512
#define NPIX   784
#define NB     8
#define SLOTS  18
#define DOUT   8705
#define NTHR   384      // poly threads: 768 butterflies / 384 = exactly 2 each
#define NTHF   512      // finalize threads

#define NTW    2048     // twiddle table entries (all stage indices < 2048)
#define APAD   4224     // 4096 + 4096/32 padding
#define SWI(i) ((i) + ((i) >> 5))

__device__ float2 g_acc2[NB][NSPEC];    // zero-init at load; re-zeroed by finalize
__device__ float2 g_acc3[NB][NSPEC];
__device__ float  g_first[NB][CCH];

typedef unsigned long long u64c;   // packed complex: lo = re, hi = im

__device__ __forceinline__ u64c cadd(u64c a, u64c b) {
    u64c r; asm("add.rn.f32x2 %0,%1,%2;" : "=l"(r) : "l"(a), "l"(b)); return r;
}
__device__ __forceinline__ u64c csub(u64c a, u64c b) {
    u64c r; asm("sub.rn.f32x2 %0,%1,%2;" : "=l"(r) : "l"(a), "l"(b)); return r;
}
__device__ __forceinline__ u64c cscale(u64c a, u64c k) {
    u64c r; asm("mul.rn.f32x2 %0,%1,%2;" : "=l"(r) : "l"(a), "l"(k)); return r;
}
__device__ __forceinline__ u64c cmuli(u64c a) {      // i*a = (-im, re)
    float x, y; asm("mov.b64 {%0,%1},%2;" : "=f"(x), "=f"(y) : "l"(a));
    float ny = -y;
    u64c r; asm("mov.b64 %0,{%1,%2};" : "=l"(r) : "f"(ny), "f"(x)); return r;
}
__device__ __forceinline__ u64c cmulmi(u64c a) {     // -i*a = (im, -re)
    float x, y; asm("mov.b64 {%0,%1},%2;" : "=f"(x), "=f"(y) : "l"(a));
    float nx = -x;
    u64c r; asm("mov.b64 %0,{%1,%2};" : "=l"(r) : "f"(y), "f"(nx)); return r;
}
__device__ __forceinline__ float2 unpk(u64c a) {
    float2 r; asm("mov.b64 {%0,%1},%2;" : "=f"(r.x), "=f"(r.y) : "l"(a)); return r;
}
__device__ __forceinline__ u64c pk2(float x, float y) {
    u64c r; asm("mov.b64 %0,{%1,%2};" : "=l"(r) : "f"(x), "f"(y)); return r;
}
__device__ __forceinline__ u64c cc2_const() {        // {CC, CC}
    u64c r; float c = 0.70710678118654752f;
    asm("mov.b64 %0,{%1,%1};" : "=l"(r) : "f"(c)); return r;
}

__device__ __forceinline__ float2 cmul(float2 a, float2 b) {
    return make_float2(a.x * b.x - a.y * b.y, a.x * b.y + a.y * b.x);
}
__device__ __forceinline__ u64c cmulc(u64c z, float wr, float wi) {
    float2 a = unpk(z);
    return pk2(a.x * wr - a.y * wi, a.x * wi + a.y * wr);
}
__device__ __forceinline__ u64c w8m1(u64c z, u64c CC2) {  // z * w8^1
    return cscale(cadd(z, cmulmi(z)), CC2);
}
__device__ __forceinline__ u64c w8m3(u64c z, u64c CC2) {  // z * w8^3
    return cscale(csub(cmulmi(z), z), CC2);
}

// ---------------- DFT16 core: loads 16 strided cells, returns y[16] ----------
__device__ __forceinline__ void bf16_fwd(const float2* __restrict__ src,
                                         int t, u64c* __restrict__ y)
{
    const u64c CC2 = cc2_const();
    const float c1 = 0.92387953251128674f, s1 = 0.38268343236508977f;
    u64c u[4][4];
    #pragma unroll
    for (int j = 0; j < 4; j++) {
        u64c a = *(const u64c*)&src[SWI(t + j * 256)];
        u64c b = *(const u64c*)&src[SWI(t + (j + 4) * 256)];
        u64c c = *(const u64c*)&src[SWI(t + (j + 8) * 256)];
        u64c d = *(const u64c*)&src[SWI(t + (j + 12) * 256)];
        u64c apc = cadd(a, c), amc = csub(a, c);
        u64c bpd = cadd(b, d);
        u64c jb  = cmuli(csub(b, d));
        u[j][0] = cadd(apc, bpd);
        u[j][1] = csub(amc, jb);
        u[j][2] = csub(apc, bpd);
        u[j][3] = cadd(amc, jb);
    }
    u[1][1] = cmulc(u[1][1],  c1, -s1);
    u[1][2] = w8m1(u[1][2], CC2);
    u[1][3] = cmulc(u[1][3],  s1, -c1);
    u[2][1] = w8m1(u[2][1], CC2);
    u[2][2] = cmulmi(u[2][2]);
    u[2][3] = w8m3(u[2][3], CC2);
    u[3][1] = cmulc(u[3][1],  s1, -c1);
    u[3][2] = w8m3(u[3][2], CC2);
    u[3][3] = cmulc(u[3][3], -c1,  s1);
    #pragma unroll
    for (int a = 0; a < 4; a++) {
        u64c p0 = u[0][a], p1 = u[1][a], p2 = u[2][a], p3 = u[3][a];
        u64c q0 = cadd(p0, p2), q1 = csub(p0, p2);
        u64c q2 = cadd(p1, p3);
        u64c jq = cmuli(csub(p1, p3));
        y[a]      = cadd(q0, q2);
        y[a + 4]  = csub(q1, jq);
        y[a + 8]  = csub(q0, q2);
        y[a + 12] = cadd(q1, jq);
    }
}

__device__ __forceinline__ void store16_tw(float2* __restrict__ dst, int o, int s,
                                           const u64c* __restrict__ y,
                                           const float2* W)
{
    dst[SWI(o)] = unpk(y[0]);
    #pragma unroll
    for (int m = 1; m < 16; m++)
        dst[SWI(o + m * s)] = cmul(unpk(y[m]), W[m - 1]);
}
__device__ __forceinline__ void store16_raw(float2* __restrict__ dst, int o, int s,
                                            const u64c* __restrict__ y)
{
    #pragma unroll
    for (int m = 0; m < 16; m++)
        *(u64c*)&dst[SWI(o + m * s)] = y[m];
}

__device__ __forceinline__ void build_W(const float2* __restrict__ tw,
                                        int p, int sh, float2* W)
{
    float2 W1 = tw[p << sh];
    float2 W2 = tw[(2 * p) << sh];
    float2 W4 = tw[(4 * p) << sh];
    float2 W8 = tw[(8 * p) << sh];
    W[0] = W1; W[1] = W2; W[2] = cmul(W1, W2); W[3] = W4;
    W[4] = cmul(W1, W4); W[5] = cmul(W2, W4); W[6] = cmul(W[2], W4);
    W[7] = W8; W[8] = cmul(W1, W8); W[9] = cmul(W2, W8);
    W[10] = cmul(W[2], W8); W[11] = cmul(W4, W8); W[12] = cmul(W[4], W8);
    W[13] = cmul(W[5], W8); W[14] = cmul(W[6], W8);
}

template<bool NOTW>
__device__ __forceinline__ void stage16_one(const float2* s0, float2* d0,
                                            const float2* __restrict__ tw,
                                            int sh, int ls, int t)
{
    int p = t >> ls;
    int q = t & ((1 << ls) - 1);
    int s = 1 << ls;
    int o = q + (p << (ls + 4));
    u64c y[16];
    bf16_fwd(s0, t, y);
    if (NOTW) {
        store16_raw(d0, o, s, y);
    } else {
        float2 W[15];
        build_W(tw, p, sh, W);
        store16_tw(d0, o, s, y, W);
    }
}

// ---------------- generic stage8 (fwd/inv) for the finalize kernel -----------
template<bool INV, bool NOTW>
__device__ __forceinline__ void stage8(const float2* __restrict__ src,
                                       float2* __restrict__ dst,
                                       const float2* __restrict__ tw,
                                       int sh, int ls, int eighth,
                                       int tid, int nt)
{
    const u64c CC2 = cc2_const();
    for (int t = tid; t < eighth; t += nt) {
        int p = t >> ls;
        int q = t & ((1 << ls) - 1);
        u64c x0 = *(const u64c*)&src[SWI(t)];
        u64c x1 = *(const u64c*)&src[SWI(t + eighth)];
        u64c x2 = *(const u64c*)&src[SWI(t + 2 * eighth)];
        u64c x3 = *(const u64c*)&src[SWI(t + 3 * eighth)];
        u64c x4 = *(const u64c*)&src[SWI(t + 4 * eighth)];
        u64c x5 = *(const u64c*)&src[SWI(t + 5 * eighth)];
        u64c x6 = *(const u64c*)&src[SWI(t + 6 * eighth)];
        u64c x7 = *(const u64c*)&src[SWI(t + 7 * eighth)];

        u64c u0 = cadd(x0, x4), u1 = csub(x0, x4);
        u64c u2 = cadd(x2, x6), u3 = csub(x2, x6);
        u64c e0 = cadd(u0, u2), e2 = csub(u0, u2);
        u64c j3 = cmuli(u3);
        u64c e1, e3;
        if (!INV) { e1 = csub(u1, j3); e3 = cadd(u1, j3); }
        else      { e1 = cadd(u1, j3); e3 = csub(u1, j3); }

        u64c v0 = cadd(x1, x5), v1 = csub(x1, x5);
        u64c v2 = cadd(x3, x7), v3 = csub(x3, x7);
        u64c o0 = cadd(v0, v2), o2 = csub(v0, v2);
        u64c k3 = cmuli(v3);
        u64c o1, o3;
        if (!INV) { o1 = csub(v1, k3); o3 = cadd(v1, k3); }
        else      { o1 = cadd(v1, k3); o3 = csub(v1, k3); }

        u64c t1, t2, t3;
        if (!INV) {
            t1 = w8m1(o1, CC2);
            t2 = cmulmi(o2);
            t3 = w8m3(o3, CC2);
        } else {
            t1 = cscale(cadd(o1, cmuli(o1)), CC2);
            t2 = cmuli(o2);
            t3 = cscale(cmuli(cadd(o3, cmuli(o3))), CC2);
        }
        u64c y0 = cadd(e0, o0), y4 = csub(e0, o0);
        u64c y1 = cadd(e1, t1), y5 = csub(e1, t1);
        u64c y2 = cadd(e2, t2), y6 = csub(e2, t2);
        u64c y3 = cadd(e3, t3), y7 = csub(e3, t3);

        int s = 1 << ls;
        int o = q + (p << (ls + 3));
        if (NOTW) {
            *(u64c*)&dst[SWI(o)]       = y0;
            *(u64c*)&dst[SWI(o + s)]   = y1;
            *(u64c*)&dst[SWI(o + 2*s)] = y2;
            *(u64c*)&dst[SWI(o + 3*s)] = y3;
            *(u64c*)&dst[SWI(o + 4*s)] = y4;
            *(u64c*)&dst[SWI(o + 5*s)] = y5;
            *(u64c*)&dst[SWI(o + 6*s)] = y6;
            *(u64c*)&dst[SWI(o + 7*s)] = y7;
        } else {
            float2 w1 = tw[p << sh];
            float2 w2 = tw[(2 * p) << sh];
            float2 w4 = tw[(4 * p) << sh];
            if (INV) { w1.y = -w1.y; w2.y = -w2.y; w4.y = -w4.y; }
            float2 w3 = cmul(w1, w2);
            float2 w5 = cmul(w1, w4);
            float2 w6 = cmul(w2, w4);
            float2 w7 = cmul(w3, w4);
            dst[SWI(o)]       = unpk(y0);
            dst[SWI(o + s)]   = cmul(unpk(y1), w1);
            dst[SWI(o + 2*s)] = cmul(unpk(y2), w2);
            dst[SWI(o + 3*s)] = cmul(unpk(y3), w3);
            dst[SWI(o + 4*s)] = cmul(unpk(y4), w4);
            dst[SWI(o + 5*s)] = cmul(unpk(y5), w5);
            dst[SWI(o + 6*s)] = cmul(unpk(y6), w6);
            dst[SWI(o + 7*s)] = cmul(unpk(y7), w7);
        }
    }
}

template<bool INV>
__device__ void fft4096_r8(float2* A, float2* B, const float2* tw, int tid, int nt)
{
    stage8<INV, false>(A, B, tw, 0, 0, 512, tid, nt); __syncthreads();
    stage8<INV, false>(B, A, tw, 3, 3, 512, tid, nt); __syncthreads();
    stage8<INV, false>(A, B, tw, 6, 6, 512, tid, nt); __syncthreads();
    stage8<INV, true >(B, A, tw, 9, 9, 512, tid, nt); __syncthreads();
}

// Hermitian unpack (2x-scaled): Z = R + i*I with R,I real spectra.
__device__ __forceinline__ void unpack2(float2 Zk, float2 Zm, float2& R, float2& I)
{
    R = make_float2(Zk.x + Zm.x,  Zk.y - Zm.y);
    I = make_float2(Zk.y + Zm.y, -(Zk.x - Zm.x));
}

__global__ void __launch_bounds__(NTHR, 1)
poly_sketch_kernel(const float* __restrict__ x,
                   const int* __restrict__ h_idx,
                   const int* __restrict__ s_bits)
{
    extern __shared__ float2 smem[];
    float2* tw = smem;                  // NTW
    float2* A1 = smem + NTW;            // pixel1 Z buffers
    float2* B1 = A1 + APAD;
    float2* A2 = B1 + APAD;             // pixel2 Z buffers
    float2* B2 = A2 + APAD;
    float2* AD = B2 + APAD;             // packed s2(p1) + i*s2(p2)
    float2* BD = AD + APAD;

    int tid  = threadIdx.x;
    int b    = blockIdx.x / SLOTS;
    int slot = blockIdx.x % SLOTS;
    bool dual = (tid < CCH - NTHR);     // threads 0..127 own a second channel

    for (int j = tid; j < NTW; j += NTHR) {
        float sn, cs;
        sincospif(-(float)j * (1.0f / 2048.0f), &sn, &cs);
        tw[j] = make_float2(cs, sn);
    }
    for (int j = tid; j < APAD; j += NTHR) {
        A1[j] = make_float2(0.f, 0.f);
        A2[j] = make_float2(0.f, 0.f);
        AD[j] = make_float2(0.f, 0.f);
    }

    int ca = tid, cb = tid + NTHR;
    int   h0a = h_idx[ca], h1a = h_idx[CCH + ca], h2a = h_idx[2 * CCH + ca];
    float s0a = (float)(2 * s_bits[ca] - 1);
    float s1a = (float)(2 * s_bits[CCH + ca] - 1);
    float s2a = (float)(2 * s_bits[2 * CCH + ca] - 1);
    int h0b = 0, h1b = 0, h2b = 0;
    float s0b = 0.f, s1b = 0.f, s2b = 0.f;
    if (dual) {
        h0b = h_idx[cb]; h1b = h_idx[CCH + cb]; h2b = h_idx[2 * CCH + cb];
        s0b = (float)(2 * s_bits[cb] - 1);
        s1b = (float)(2 * s_bits[CCH + cb] - 1);
        s2b = (float)(2 * s_bits[2 * CCH + cb] - 1);
    }
    __syncthreads();

    float2 a2[6], a3[6], m2, m3;
    #pragma unroll
    for (int i = 0; i < 6; i++) { a2[i] = make_float2(0.f, 0.f); a3[i] = make_float2(0.f, 0.f); }
    m2 = make_float2(0.f, 0.f); m3 = make_float2(0.f, 0.f);
    float xsa = 0.f, xsb = 0.f;

    const float* xra = x + (size_t)b * NPIX * CCH + ca;
    const float* xrb = x + (size_t)b * NPIX * CCH + cb;
    float x1a = xra[(size_t)slot * CCH];
    float x2a = (slot + SLOTS < NPIX) ? xra[(size_t)(slot + SLOTS) * CCH] : 0.f;
    float x1b = 0.f, x2b = 0.f;
    if (dual) {
        x1b = xrb[(size_t)slot * CCH];
        x2b = (slot + SLOTS < NPIX) ? xrb[(size_t)(slot + SLOTS) * CCH] : 0.f;
    }

    float2 *sA1 = A1, *sB1 = B1, *sA2 = A2, *sB2 = B2, *sAD = AD, *sBD = BD;

    for (int pix = slot; pix < NPIX; pix += 2 * SLOTS) {
        atomicAdd(&sA1[SWI(h0a)].x, x1a * s0a);
        atomicAdd(&sA1[SWI(h1a)].y, x1a * s1a);
        atomicAdd(&sA2[SWI(h0a)].x, x2a * s0a);
        atomicAdd(&sA2[SWI(h1a)].y, x2a * s1a);
        atomicAdd(&sAD[SWI(h2a)].x, x1a * s2a);
        atomicAdd(&sAD[SWI(h2a)].y, x2a * s2a);
        xsa += x1a + x2a;
        if (dual) {
            atomicAdd(&sA1[SWI(h0b)].x, x1b * s0b);
            atomicAdd(&sA1[SWI(h1b)].y, x1b * s1b);
            atomicAdd(&sA2[SWI(h0b)].x, x2b * s0b);
            atomicAdd(&sA2[SWI(h1b)].y, x2b * s1b);
            atomicAdd(&sAD[SWI(h2b)].x, x1b * s2b);
            atomicAdd(&sAD[SWI(h2b)].y, x2b * s2b);
            xsb += x1b + x2b;
        }
        __syncthreads();

        int n1 = pix + 2 * SLOTS, n2 = pix + 3 * SLOTS;
        float xn1a = (n1 < NPIX) ? xra[(size_t)n1 * CCH] : 0.f;
        float xn2a = (n2 < NPIX) ? xra[(size_t)n2 * CCH] : 0.f;
        float xn1b = 0.f, xn2b = 0.f;
        if (dual) {
            xn1b = (n1 < NPIX) ? xrb[(size_t)n1 * CCH] : 0.f;
            xn2b = (n2 < NPIX) ? xrb[(size_t)n2 * CCH] : 0.f;
        }

        // balanced dispatch: items t and t+384 of concatenated [Z1|Z2|D] space
        // phase 1 (ls=0, sh=0)
        if (tid < 256) stage16_one<false>(sA1, sB1, tw, 0, 0, tid);
        else           stage16_one<false>(sA2, sB2, tw, 0, 0, tid - 256);
        if (tid < 128) stage16_one<false>(sA2, sB2, tw, 0, 0, tid + 128);
        else           stage16_one<false>(sAD, sBD, tw, 0, 0, tid - 128);
        __syncthreads();
        // phase 2 (ls=4, sh=4)
        if (tid < 256) stage16_one<false>(sB1, sA1, tw, 4, 4, tid);
        else           stage16_one<false>(sB2, sA2, tw, 4, 4, tid - 256);
        if (tid < 128) stage16_one<false>(sB2, sA2, tw, 4, 4, tid + 128);
        else           stage16_one<false>(sBD, sAD, tw, 4, 4, tid - 128);
        __syncthreads();
        // phase 3 (ls=8, no twiddles)
        if (tid < 256) stage16_one<true>(sA1, sB1, tw, 0, 8, tid);
        else           stage16_one<true>(sA2, sB2, tw, 0, 8, tid - 256);
        if (tid < 128) stage16_one<true>(sA2, sB2, tw, 0, 8, tid + 128);
        else           stage16_one<true>(sAD, sBD, tw, 0, 8, tid - 128);
        __syncthreads();
        // spectra: Z1 in sB1, Z2 in sB2, Dspec in sBD

        #pragma unroll
        for (int ii = 0; ii < 3; ii++) {
            int k = tid + ii * NTHR;               // 0..1151; use k < 1024
            if (k < 1024) {
                int km = (NFFT - k) & (NFFT - 1);
                int kb = 2048 - k;
                int kc = 2048 + k;
                float2 Z1k = sB1[SWI(k)],  Z1m = sB1[SWI(km)];
                float2 Z1b = sB1[SWI(kb)], Z1c = sB1[SWI(kc)];
                float2 Z2k = sB2[SWI(k)],  Z2m = sB2[SWI(km)];
                float2 Z2b = sB2[SWI(kb)], Z2c = sB2[SWI(kc)];
                float2 Dk  = sBD[SWI(k)],  Dm  = sBD[SWI(km)];
                float2 Db  = sBD[SWI(kb)], Dc  = sBD[SWI(kc)];

                float2 F0, F1, G0, G1, H0, H1;
                unpack2(Z1k, Z1m, F0, F1);
                unpack2(Z2k, Z2m, G0, G1);
                unpack2(Dk,  Dm,  H0, H1);
                float2 P2 = cmul(F0, F1), P3 = cmul(P2, H0);
                float2 Q2 = cmul(G0, G1), Q3 = cmul(Q2, H1);
                a2[2*ii].x += P2.x + Q2.x; a2[2*ii].y += P2.y + Q2.y;
                a3[2*ii].x += P3.x + Q3.x; a3[2*ii].y += P3.y + Q3.y;

                unpack2(Z1b, Z1c, F0, F1);
                unpack2(Z2b, Z2c, G0, G1);
                unpack2(Db,  Dc,  H0, H1);
                P2 = cmul(F0, F1); P3 = cmul(P2, H0);
                Q2 = cmul(G0, G1); Q3 = cmul(Q2, H1);
                a2[2*ii+1].x += P2.x + Q2.x; a2[2*ii+1].y += P2.y + Q2.y;
                a3[2*ii+1].x += P3.x + Q3.x; a3[2*ii+1].y += P3.y + Q3.y;

                float2 z = make_float2(0.f, 0.f);
                sB1[SWI(k)] = z; sB1[SWI(km)] = z; sB1[SWI(kb)] = z; sB1[SWI(kc)] = z;
                sB2[SWI(k)] = z; sB2[SWI(km)] = z; sB2[SWI(kb)] = z; sB2[SWI(kc)] = z;
                sBD[SWI(k)] = z; sBD[SWI(km)] = z; sBD[SWI(kb)] = z; sBD[SWI(kc)] = z;
            }
        }
        if (tid == 0) {                       // self-paired bin 1024
            float2 Z1k = sB1[SWI(1024)], Z1m = sB1[SWI(3072)];
            float2 Z2k = sB2[SWI(1024)], Z2m = sB2[SWI(3072)];
            float2 Dk  = sBD[SWI(1024)], Dm  = sBD[SWI(3072)];
            float2 F0, F1, G0, G1, H0, H1;
            unpack2(Z1k, Z1m, F0, F1);
            unpack2(Z2k, Z2m, G0, G1);
            unpack2(Dk,  Dm,  H0, H1);
            float2 P2 = cmul(F0, F1), P3 = cmul(P2, H0);
            float2 Q2 = cmul(G0, G1), Q3 = cmul(Q2, H1);
            m2.x += P2.x + Q2.x; m2.y += P2.y + Q2.y;
            m3.x += P3.x + Q3.x; m3.y += P3.y + Q3.y;
            float2 z = make_float2(0.f, 0.f);
            sB1[SWI(1024)] = z; sB1[SWI(3072)] = z;
            sB2[SWI(1024)] = z; sB2[SWI(3072)] = z;
            sBD[SWI(1024)] = z; sBD[SWI(3072)] = z;
        }

        float2* t0;
        t0 = sA1; sA1 = sB1; sB1 = t0;
        t0 = sA2; sA2 = sB2; sB2 = t0;
        t0 = sAD; sAD = sBD; sBD = t0;

        x1a = xn1a; x2a = xn2a; x1b = xn1b; x2b = xn2b;
        __syncthreads();
    }

    #pragma unroll
    for (int ii = 0; ii < 3; ii++) {
        int k = tid + ii * NTHR;
        if (k < 1024) {
            atomicAdd(&g_acc2[b][k].x, a2[2*ii].x);
            atomicAdd(&g_acc2[b][k].y, a2[2*ii].y);
            atomicAdd(&g_acc3[b][k].x, a3[2*ii].x);
            atomicAdd(&g_acc3[b][k].y, a3[2*ii].y);
            atomicAdd(&g_acc2[b][2048 - k].x, a2[2*ii+1].x);
            atomicAdd(&g_acc2[b][2048 - k].y, a2[2*ii+1].y);
            atomicAdd(&g_acc3[b][2048 - k].x, a3[2*ii+1].x);
            atomicAdd(&g_acc3[b][2048 - k].y, a3[2*ii+1].y);
        }
    }
    if (tid == 0) {
        atomicAdd(&g_acc2[b][1024].x, m2.x);
        atomicAdd(&g_acc2[b][1024].y, m2.y);
        atomicAdd(&g_acc3[b][1024].x, m3.x);
        atomicAdd(&g_acc3[b][1024].y, m3.y);
    }
    atomicAdd(&g_first[b][ca], xsa);
    if (dual) atomicAdd(&g_first[b][cb], xsb);
}

__global__ void __launch_bounds__(NTHF, 1)
finalize_kernel(const float* __restrict__ alpha, float* __restrict__ out)
{
    extern __shared__ float2 smem[];
    float2* tw  = smem;                 // NTW
    float2* A   = smem + NTW;
    float2* B   = A + APAD;
    float*  phi = (float*)(B + APAD);   // 8712 floats
    __shared__ float red[17];

    int tid = threadIdx.x;
    int b   = blockIdx.x;

    for (int j = tid; j < NTW; j += NTHF) {
        float sn, cs;
        sincospif(-(float)j * (1.0f / 2048.0f), &sn, &cs);
        tw[j] = make_float2(cs, sn);
    }
    __syncthreads();

    // accumulators carry 4x (acc2) and 8x (acc3) -> fold 0.25 / 0.125 here
    const float inv_n = 1.0f / ((float)NPIX * (float)NFFT);

    for (int i = tid; i < NFFT; i += NTHF) {
        if (i <= NHALF) A[SWI(i)] = g_acc2[b][i];
        else { float2 v = g_acc2[b][NFFT - i]; A[SWI(i)] = make_float2(v.x, -v.y); }
    }
    __syncthreads();
    // re-zero acc2 for the next launch (safe: all reads completed at the barrier)
    for (int i = tid; i < NSPEC; i += NTHF) g_acc2[b][i] = make_float2(0.f, 0.f);
    fft4096_r8<true>(A, B, tw, tid, NTHF);
    {
        float a2c = alpha[2] * inv_n * 0.25f;
        for (int i = tid; i < NFFT; i += NTHF) phi[513 + i] = A[SWI(i)].x * a2c;
    }
    __syncthreads();

    for (int i = tid; i < NFFT; i += NTHF) {
        if (i <= NHALF) A[SWI(i)] = g_acc3[b][i];
        else { float2 v = g_acc3[b][NFFT - i]; A[SWI(i)] = make_float2(v.x, -v.y); }
    }
    __syncthreads();
    for (int i = tid; i < NSPEC; i += NTHF) g_acc3[b][i] = make_float2(0.f, 0.f);
    fft4096_r8<true>(A, B, tw, tid, NTHF);
    {
        float a3c = alpha[3] * inv_n * 0.125f;
        for (int i = tid; i < NFFT; i += NTHF) phi[513 + NFFT + i] = A[SWI(i)].x * a3c;
    }

    if (tid == 0) phi[0] = alpha[0];
    phi[1 + tid] = alpha[1] * g_first[b][tid] * (1.0f / (float)NPIX);
    g_first[b][tid] = 0.f;              // exclusive read -> safe inline re-zero
    __syncthreads();

    float lsum = 0.f;
    for (int i = tid; i < DOUT; i += NTHF) {
        float v = phi[i];
        float r;
        if (v > 0.f)      r =  sqrtf(v + 1e-12f);
        else if (v < 0.f) r = -sqrtf(-v + 1e-12f);
        else              r = 0.f;
        phi[i] = r;
        lsum += r * r;
    }
    #pragma unroll
    for (int off = 16; off > 0; off >>= 1)
        lsum += __shfl_down_sync(0xffffffffu, lsum, off);
    if ((tid & 31) == 0) red[tid >> 5] = lsum;
    __syncthreads();
    if (tid == 0) {
        float s = 0.f;
        #pragma unroll
        for (int k = 0; k < 16; k++) s += red[k];
        red[16] = 1.0f / sqrtf(s);
    }
    __syncthreads();
    float rn = red[16];
    for (int i = tid; i < DOUT; i += NTHF)
        out[(size_t)b * DOUT + i] = phi[i] * rn;
}

extern "C" void kernel_launch(void* const* d_in, const int* in_sizes, int n_in,
                              void* d_out, int out_size)
{
    const float* x     = (const float*)d_in[0];
    const float* alpha = (const float*)d_in[1];
    const int*   h     = (const int*)d_in[2];
    const int*   sb    = (const int*)d_in[3];
    float*       out   = (float*)d_out;

    const int MAIN_SMEM = (NTW + 6 * APAD) * (int)sizeof(float2);            // 219136
    const int FIN_SMEM  = (NTW + 2 * APAD) * (int)sizeof(float2) + 8712 * 4; // 118816

    cudaFuncSetAttribute(poly_sketch_kernel,
                         cudaFuncAttributeMaxDynamicSharedMemorySize, MAIN_SMEM);
    cudaFuncSetAttribute(finalize_kernel,
                         cudaFuncAttributeMaxDynamicSharedMemorySize, FIN_SMEM);

    poly_sketch_kernel<<<NB * SLOTS, NTHR, MAIN_SMEM>>>(x, h, sb);
    finalize_kernel<<<NB, NTHF, FIN_SMEM>>>(alpha, out);
}

// round 15
// speedup vs baseline: 1.0802x; 1.0802x over previous
#include <cuda_runtime.h>
#include <math.h>

#define NFFT   4096
#define NHALF  2048
#define NSPEC  2049
#define CCH    512
#define NPIX   784
#define NB     8
#define SLOTS  18
#define DOUT   8705
#define NTHR   512
#define NTHF   512

#define NTW    2048     // twiddle table entries (all stage indices < 2048)
#define APAD   4224     // 4096 + 4096/32 padding
#define SWI(i) ((i) + ((i) >> 5))

__device__ float2 g_acc2[NB][NSPEC];    // zero at load; re-zeroed by finalize
__device__ float2 g_acc3[NB][NSPEC];
__device__ float  g_first[NB][CCH];

typedef unsigned long long u64c;   // packed complex: lo = re, hi = im

__device__ __forceinline__ u64c cadd(u64c a, u64c b) {
    u64c r; asm("add.rn.f32x2 %0,%1,%2;" : "=l"(r) : "l"(a), "l"(b)); return r;
}
__device__ __forceinline__ u64c csub(u64c a, u64c b) {
    u64c r; asm("sub.rn.f32x2 %0,%1,%2;" : "=l"(r) : "l"(a), "l"(b)); return r;
}
__device__ __forceinline__ u64c cscale(u64c a, u64c k) {
    u64c r; asm("mul.rn.f32x2 %0,%1,%2;" : "=l"(r) : "l"(a), "l"(k)); return r;
}
__device__ __forceinline__ u64c cmuli(u64c a) {      // i*a = (-im, re)
    float x, y; asm("mov.b64 {%0,%1},%2;" : "=f"(x), "=f"(y) : "l"(a));
    float ny = -y;
    u64c r; asm("mov.b64 %0,{%1,%2};" : "=l"(r) : "f"(ny), "f"(x)); return r;
}
__device__ __forceinline__ u64c cmulmi(u64c a) {     // -i*a = (im, -re)
    float x, y; asm("mov.b64 {%0,%1},%2;" : "=f"(x), "=f"(y) : "l"(a));
    float nx = -x;
    u64c r; asm("mov.b64 %0,{%1,%2};" : "=l"(r) : "f"(y), "f"(nx)); return r;
}
__device__ __forceinline__ float2 unpk(u64c a) {
    float2 r; asm("mov.b64 {%0,%1},%2;" : "=f"(r.x), "=f"(r.y) : "l"(a)); return r;
}
__device__ __forceinline__ u64c pk2(float x, float y) {
    u64c r; asm("mov.b64 %0,{%1,%2};" : "=l"(r) : "f"(x), "f"(y)); return r;
}
__device__ __forceinline__ u64c cc2_const() {        // {CC, CC}
    u64c r; float c = 0.70710678118654752f;
    asm("mov.b64 %0,{%1,%1};" : "=l"(r) : "f"(c)); return r;
}

__device__ __forceinline__ float2 cmul(float2 a, float2 b) {
    return make_float2(a.x * b.x - a.y * b.y, a.x * b.y + a.y * b.x);
}
__device__ __forceinline__ u64c cmulc(u64c z, float wr, float wi) {
    float2 a = unpk(z);
    return pk2(a.x * wr - a.y * wi, a.x * wi + a.y * wr);
}
__device__ __forceinline__ u64c w8m1(u64c z, u64c CC2) {  // z * w8^1
    return cscale(cadd(z, cmulmi(z)), CC2);
}
__device__ __forceinline__ u64c w8m3(u64c z, u64c CC2) {  // z * w8^3
    return cscale(csub(cmulmi(z), z), CC2);
}

// ---------------- DFT16 core: loads 16 strided cells, returns y[16] ----------
__device__ __forceinline__ void bf16_fwd(const float2* __restrict__ src,
                                         int t, u64c* __restrict__ y)
{
    const u64c CC2 = cc2_const();
    const float c1 = 0.92387953251128674f, s1 = 0.38268343236508977f;
    u64c u[4][4];
    #pragma unroll
    for (int j = 0; j < 4; j++) {
        u64c a = *(const u64c*)&src[SWI(t + j * 256)];
        u64c b = *(const u64c*)&src[SWI(t + (j + 4) * 256)];
        u64c c = *(const u64c*)&src[SWI(t + (j + 8) * 256)];
        u64c d = *(const u64c*)&src[SWI(t + (j + 12) * 256)];
        u64c apc = cadd(a, c), amc = csub(a, c);
        u64c bpd = cadd(b, d);
        u64c jb  = cmuli(csub(b, d));
        u[j][0] = cadd(apc, bpd);
        u[j][1] = csub(amc, jb);
        u[j][2] = csub(apc, bpd);
        u[j][3] = cadd(amc, jb);
    }
    u[1][1] = cmulc(u[1][1],  c1, -s1);
    u[1][2] = w8m1(u[1][2], CC2);
    u[1][3] = cmulc(u[1][3],  s1, -c1);
    u[2][1] = w8m1(u[2][1], CC2);
    u[2][2] = cmulmi(u[2][2]);
    u[2][3] = w8m3(u[2][3], CC2);
    u[3][1] = cmulc(u[3][1],  s1, -c1);
    u[3][2] = w8m3(u[3][2], CC2);
    u[3][3] = cmulc(u[3][3], -c1,  s1);
    #pragma unroll
    for (int a = 0; a < 4; a++) {
        u64c p0 = u[0][a], p1 = u[1][a], p2 = u[2][a], p3 = u[3][a];
        u64c q0 = cadd(p0, p2), q1 = csub(p0, p2);
        u64c q2 = cadd(p1, p3);
        u64c jq = cmuli(csub(p1, p3));
        y[a]      = cadd(q0, q2);
        y[a + 4]  = csub(q1, jq);
        y[a + 8]  = csub(q0, q2);
        y[a + 12] = cadd(q1, jq);
    }
}

__device__ __forceinline__ void store16_tw(float2* __restrict__ dst, int o, int s,
                                           const u64c* __restrict__ y,
                                           const float2* W)
{
    dst[SWI(o)] = unpk(y[0]);
    #pragma unroll
    for (int m = 1; m < 16; m++)
        dst[SWI(o + m * s)] = cmul(unpk(y[m]), W[m - 1]);
}
__device__ __forceinline__ void store16_raw(float2* __restrict__ dst, int o, int s,
                                            const u64c* __restrict__ y)
{
    #pragma unroll
    for (int m = 0; m < 16; m++)
        *(u64c*)&dst[SWI(o + m * s)] = y[m];
}

__device__ __forceinline__ void build_W(const float2* __restrict__ tw,
                                        int p, int sh, float2* W)
{
    float2 W1 = tw[p << sh];
    float2 W2 = tw[(2 * p) << sh];
    float2 W4 = tw[(4 * p) << sh];
    float2 W8 = tw[(8 * p) << sh];
    W[0] = W1; W[1] = W2; W[2] = cmul(W1, W2); W[3] = W4;
    W[4] = cmul(W1, W4); W[5] = cmul(W2, W4); W[6] = cmul(W[2], W4);
    W[7] = W8; W[8] = cmul(W1, W8); W[9] = cmul(W2, W8);
    W[10] = cmul(W[2], W8); W[11] = cmul(W4, W8); W[12] = cmul(W[4], W8);
    W[13] = cmul(W[5], W8); W[14] = cmul(W[6], W8);
}

// pair stage: two FFTs (same butterfly index) share one twiddle set
template<bool NOTW>
__device__ __forceinline__ void stage16_pair(const float2* s0, float2* d0,
                                             const float2* s1, float2* d1,
                                             const float2* __restrict__ tw,
                                             int sh, int ls, int t)
{
    int p = t >> ls;
    int q = t & ((1 << ls) - 1);
    int s = 1 << ls;
    int o = q + (p << (ls + 4));
    u64c y[16];
    if (NOTW) {
        bf16_fwd(s0, t, y); store16_raw(d0, o, s, y);
        bf16_fwd(s1, t, y); store16_raw(d1, o, s, y);
    } else {
        float2 W[15];
        build_W(tw, p, sh, W);
        bf16_fwd(s0, t, y); store16_tw(d0, o, s, y, W);
        bf16_fwd(s1, t, y); store16_tw(d1, o, s, y, W);
    }
}

template<bool NOTW>
__device__ __forceinline__ void stage16_one(const float2* s0, float2* d0,
                                            const float2* __restrict__ tw,
                                            int sh, int ls, int t)
{
    int p = t >> ls;
    int q = t & ((1 << ls) - 1);
    int s = 1 << ls;
    int o = q + (p << (ls + 4));
    u64c y[16];
    bf16_fwd(s0, t, y);
    if (NOTW) {
        store16_raw(d0, o, s, y);
    } else {
        float2 W[15];
        build_W(tw, p, sh, W);
        store16_tw(d0, o, s, y, W);
    }
}

// ---------------- generic stage8 (fwd/inv) for the finalize kernel -----------
template<bool INV, bool NOTW>
__device__ __forceinline__ void stage8(const float2* __restrict__ src,
                                       float2* __restrict__ dst,
                                       const float2* __restrict__ tw,
                                       int sh, int ls, int eighth,
                                       int tid, int nt)
{
    const u64c CC2 = cc2_const();
    for (int t = tid; t < eighth; t += nt) {
        int p = t >> ls;
        int q = t & ((1 << ls) - 1);
        u64c x0 = *(const u64c*)&src[SWI(t)];
        u64c x1 = *(const u64c*)&src[SWI(t + eighth)];
        u64c x2 = *(const u64c*)&src[SWI(t + 2 * eighth)];
        u64c x3 = *(const u64c*)&src[SWI(t + 3 * eighth)];
        u64c x4 = *(const u64c*)&src[SWI(t + 4 * eighth)];
        u64c x5 = *(const u64c*)&src[SWI(t + 5 * eighth)];
        u64c x6 = *(const u64c*)&src[SWI(t + 6 * eighth)];
        u64c x7 = *(const u64c*)&src[SWI(t + 7 * eighth)];

        u64c u0 = cadd(x0, x4), u1 = csub(x0, x4);
        u64c u2 = cadd(x2, x6), u3 = csub(x2, x6);
        u64c e0 = cadd(u0, u2), e2 = csub(u0, u2);
        u64c j3 = cmuli(u3);
        u64c e1, e3;
        if (!INV) { e1 = csub(u1, j3); e3 = cadd(u1, j3); }
        else      { e1 = cadd(u1, j3); e3 = csub(u1, j3); }

        u64c v0 = cadd(x1, x5), v1 = csub(x1, x5);
        u64c v2 = cadd(x3, x7), v3 = csub(x3, x7);
        u64c o0 = cadd(v0, v2), o2 = csub(v0, v2);
        u64c k3 = cmuli(v3);
        u64c o1, o3;
        if (!INV) { o1 = csub(v1, k3); o3 = cadd(v1, k3); }
        else      { o1 = cadd(v1, k3); o3 = csub(v1, k3); }

        u64c t1, t2, t3;
        if (!INV) {
            t1 = w8m1(o1, CC2);
            t2 = cmulmi(o2);
            t3 = w8m3(o3, CC2);
        } else {
            t1 = cscale(cadd(o1, cmuli(o1)), CC2);
            t2 = cmuli(o2);
            t3 = cscale(cmuli(cadd(o3, cmuli(o3))), CC2);
        }
        u64c y0 = cadd(e0, o0), y4 = csub(e0, o0);
        u64c y1 = cadd(e1, t1), y5 = csub(e1, t1);
        u64c y2 = cadd(e2, t2), y6 = csub(e2, t2);
        u64c y3 = cadd(e3, t3), y7 = csub(e3, t3);

        int s = 1 << ls;
        int o = q + (p << (ls + 3));
        if (NOTW) {
            *(u64c*)&dst[SWI(o)]       = y0;
            *(u64c*)&dst[SWI(o + s)]   = y1;
            *(u64c*)&dst[SWI(o + 2*s)] = y2;
            *(u64c*)&dst[SWI(o + 3*s)] = y3;
            *(u64c*)&dst[SWI(o + 4*s)] = y4;
            *(u64c*)&dst[SWI(o + 5*s)] = y5;
            *(u64c*)&dst[SWI(o + 6*s)] = y6;
            *(u64c*)&dst[SWI(o + 7*s)] = y7;
        } else {
            float2 w1 = tw[p << sh];
            float2 w2 = tw[(2 * p) << sh];
            float2 w4 = tw[(4 * p) << sh];
            if (INV) { w1.y = -w1.y; w2.y = -w2.y; w4.y = -w4.y; }
            float2 w3 = cmul(w1, w2);
            float2 w5 = cmul(w1, w4);
            float2 w6 = cmul(w2, w4);
            float2 w7 = cmul(w3, w4);
            dst[SWI(o)]       = unpk(y0);
            dst[SWI(o + s)]   = cmul(unpk(y1), w1);
            dst[SWI(o + 2*s)] = cmul(unpk(y2), w2);
            dst[SWI(o + 3*s)] = cmul(unpk(y3), w3);
            dst[SWI(o + 4*s)] = cmul(unpk(y4), w4);
            dst[SWI(o + 5*s)] = cmul(unpk(y5), w5);
            dst[SWI(o + 6*s)] = cmul(unpk(y6), w6);
            dst[SWI(o + 7*s)] = cmul(unpk(y7), w7);
        }
    }
}

template<bool INV>
__device__ void fft4096_r8(float2* A, float2* B, const float2* tw, int tid, int nt)
{
    stage8<INV, false>(A, B, tw, 0, 0, 512, tid, nt); __syncthreads();
    stage8<INV, false>(B, A, tw, 3, 3, 512, tid, nt); __syncthreads();
    stage8<INV, false>(A, B, tw, 6, 6, 512, tid, nt); __syncthreads();
    stage8<INV, true >(B, A, tw, 9, 9, 512, tid, nt); __syncthreads();
}

// Hermitian unpack (2x-scaled): Z = R + i*I with R,I real spectra.
__device__ __forceinline__ void unpack2(float2 Zk, float2 Zm, float2& R, float2& I)
{
    R = make_float2(Zk.x + Zm.x,  Zk.y - Zm.y);
    I = make_float2(Zk.y + Zm.y, -(Zk.x - Zm.x));
}

__global__ void __launch_bounds__(NTHR, 1)
poly_sketch_kernel(const float* __restrict__ x,
                   const int* __restrict__ h_idx,
                   const int* __restrict__ s_bits)
{
    extern __shared__ float2 smem[];
    float2* tw = smem;                  // NTW
    float2* A1 = smem + NTW;            // pixel1 Z buffers
    float2* B1 = A1 + APAD;
    float2* A2 = B1 + APAD;             // pixel2 Z buffers
    float2* B2 = A2 + APAD;
    float2* AD = B2 + APAD;             // packed s2(p1) + i*s2(p2)
    float2* BD = AD + APAD;

    int tid  = threadIdx.x;
    int b    = blockIdx.x / SLOTS;
    int slot = blockIdx.x % SLOTS;

    for (int j = tid; j < NTW; j += NTHR) {
        float sn, cs;
        sincospif(-(float)j * (1.0f / 2048.0f), &sn, &cs);
        tw[j] = make_float2(cs, sn);
    }
    for (int j = tid; j < APAD; j += NTHR) {
        A1[j] = make_float2(0.f, 0.f);
        A2[j] = make_float2(0.f, 0.f);
        AD[j] = make_float2(0.f, 0.f);
    }

    int   h0 = h_idx[tid], h1 = h_idx[CCH + tid], h2 = h_idx[2 * CCH + tid];
    float s0 = (float)(2 * s_bits[tid] - 1);
    float s1 = (float)(2 * s_bits[CCH + tid] - 1);
    float s2 = (float)(2 * s_bits[2 * CCH + tid] - 1);
    __syncthreads();

    float2 a2[4], a3[4], m2, m3;
    #pragma unroll
    for (int i = 0; i < 4; i++) { a2[i] = make_float2(0.f, 0.f); a3[i] = make_float2(0.f, 0.f); }
    m2 = make_float2(0.f, 0.f); m3 = make_float2(0.f, 0.f);
    float xsum = 0.f;

    const float* xrow = x + (size_t)b * NPIX * CCH + tid;
    float x1 = xrow[(size_t)slot * CCH];
    float x2 = (slot + SLOTS < NPIX) ? xrow[(size_t)(slot + SLOTS) * CCH] : 0.f;

    float2 *sA1 = A1, *sB1 = B1, *sA2 = A2, *sB2 = B2, *sAD = AD, *sBD = BD;

    for (int pix = slot; pix < NPIX; pix += 2 * SLOTS) {
        atomicAdd(&sA1[SWI(h0)].x, x1 * s0);
        atomicAdd(&sA1[SWI(h1)].y, x1 * s1);
        atomicAdd(&sA2[SWI(h0)].x, x2 * s0);
        atomicAdd(&sA2[SWI(h1)].y, x2 * s1);
        atomicAdd(&sAD[SWI(h2)].x, x1 * s2);
        atomicAdd(&sAD[SWI(h2)].y, x2 * s2);
        xsum += x1 + x2;
        __syncthreads();

        int n1 = pix + 2 * SLOTS, n2 = pix + 3 * SLOTS;
        float xn1 = (n1 < NPIX) ? xrow[(size_t)n1 * CCH] : 0.f;
        float xn2 = (n2 < NPIX) ? xrow[(size_t)n2 * CCH] : 0.f;

        // phase 1 (ls=0, sh=0)
        if (tid < 256) stage16_pair<false>(sA1, sB1, sAD, sBD, tw, 0, 0, tid);
        else           stage16_one<false>(sA2, sB2, tw, 0, 0, tid - 256);
        __syncthreads();
        // phase 2 (ls=4, sh=4)
        if (tid < 256) stage16_pair<false>(sB1, sA1, sBD, sAD, tw, 4, 4, tid);
        else           stage16_one<false>(sB2, sA2, tw, 4, 4, tid - 256);
        __syncthreads();
        // phase 3 (ls=8, no twiddles)
        if (tid < 256) stage16_pair<true>(sA1, sB1, sAD, sBD, tw, 0, 8, tid);
        else           stage16_one<true>(sA2, sB2, tw, 0, 8, tid - 256);
        __syncthreads();
        // spectra: Z1 in sB1, Z2 in sB2, Dspec in sBD

        #pragma unroll
        for (int jj = 0; jj < 2; jj++) {
            int k  = tid + jj * 512;               // 0..1023
            int km = (NFFT - k) & (NFFT - 1);
            int kb = 2048 - k;
            int kc = 2048 + k;
            float2 Z1k = sB1[SWI(k)],  Z1m = sB1[SWI(km)];
            float2 Z1b = sB1[SWI(kb)], Z1c = sB1[SWI(kc)];
            float2 Z2k = sB2[SWI(k)],  Z2m = sB2[SWI(km)];
            float2 Z2b = sB2[SWI(kb)], Z2c = sB2[SWI(kc)];
            float2 Dk  = sBD[SWI(k)],  Dm  = sBD[SWI(km)];
            float2 Db  = sBD[SWI(kb)], Dc  = sBD[SWI(kc)];

            float2 F0, F1, G0, G1, H0, H1;
            unpack2(Z1k, Z1m, F0, F1);
            unpack2(Z2k, Z2m, G0, G1);
            unpack2(Dk,  Dm,  H0, H1);
            float2 P2 = cmul(F0, F1), P3 = cmul(P2, H0);
            float2 Q2 = cmul(G0, G1), Q3 = cmul(Q2, H1);
            a2[2*jj].x += P2.x + Q2.x; a2[2*jj].y += P2.y + Q2.y;
            a3[2*jj].x += P3.x + Q3.x; a3[2*jj].y += P3.y + Q3.y;

            unpack2(Z1b, Z1c, F0, F1);
            unpack2(Z2b, Z2c, G0, G1);
            unpack2(Db,  Dc,  H0, H1);
            P2 = cmul(F0, F1); P3 = cmul(P2, H0);
            Q2 = cmul(G0, G1); Q3 = cmul(Q2, H1);
            a2[2*jj+1].x += P2.x + Q2.x; a2[2*jj+1].y += P2.y + Q2.y;
            a3[2*jj+1].x += P3.x + Q3.x; a3[2*jj+1].y += P3.y + Q3.y;

            float2 z = make_float2(0.f, 0.f);
            sB1[SWI(k)] = z; sB1[SWI(km)] = z; sB1[SWI(kb)] = z; sB1[SWI(kc)] = z;
            sB2[SWI(k)] = z; sB2[SWI(km)] = z; sB2[SWI(kb)] = z; sB2[SWI(kc)] = z;
            sBD[SWI(k)] = z; sBD[SWI(km)] = z; sBD[SWI(kb)] = z; sBD[SWI(kc)] = z;
        }
        if (tid == 0) {                       // self-paired bin 1024
            float2 Z1k = sB1[SWI(1024)], Z1m = sB1[SWI(3072)];
            float2 Z2k = sB2[SWI(1024)], Z2m = sB2[SWI(3072)];
            float2 Dk  = sBD[SWI(1024)], Dm  = sBD[SWI(3072)];
            float2 F0, F1, G0, G1, H0, H1;
            unpack2(Z1k, Z1m, F0, F1);
            unpack2(Z2k, Z2m, G0, G1);
            unpack2(Dk,  Dm,  H0, H1);
            float2 P2 = cmul(F0, F1), P3 = cmul(P2, H0);
            float2 Q2 = cmul(G0, G1), Q3 = cmul(Q2, H1);
            m2.x += P2.x + Q2.x; m2.y += P2.y + Q2.y;
            m3.x += P3.x + Q3.x; m3.y += P3.y + Q3.y;
            float2 z = make_float2(0.f, 0.f);
            sB1[SWI(1024)] = z; sB1[SWI(3072)] = z;
            sB2[SWI(1024)] = z; sB2[SWI(3072)] = z;
            sBD[SWI(1024)] = z; sBD[SWI(3072)] = z;
        }

        float2* t0;
        t0 = sA1; sA1 = sB1; sB1 = t0;
        t0 = sA2; sA2 = sB2; sB2 = t0;
        t0 = sAD; sAD = sBD; sBD = t0;

        x1 = xn1; x2 = xn2;
        __syncthreads();
    }

    int bins[4] = { tid, 2048 - tid, tid + 512, 1536 - tid };
    #pragma unroll
    for (int i = 0; i < 4; i++) {
        atomicAdd(&g_acc2[b][bins[i]].x, a2[i].x);
        atomicAdd(&g_acc2[b][bins[i]].y, a2[i].y);
        atomicAdd(&g_acc3[b][bins[i]].x, a3[i].x);
        atomicAdd(&g_acc3[b][bins[i]].y, a3[i].y);
    }
    if (tid == 0) {
        atomicAdd(&g_acc2[b][1024].x, m2.x);
        atomicAdd(&g_acc2[b][1024].y, m2.y);
        atomicAdd(&g_acc3[b][1024].x, m3.x);
        atomicAdd(&g_acc3[b][1024].y, m3.y);
    }
    atomicAdd(&g_first[b][tid], xsum);
}

__global__ void __launch_bounds__(NTHF, 1)
finalize_kernel(const float* __restrict__ alpha, float* __restrict__ out)
{
    extern __shared__ float2 smem[];
    float2* tw  = smem;                 // NTW
    float2* A   = smem + NTW;
    float2* B   = A + APAD;
    float*  phi = (float*)(B + APAD);   // 8712 floats
    __shared__ float red[17];

    int tid = threadIdx.x;
    int b   = blockIdx.x;

    for (int j = tid; j < NTW; j += NTHF) {
        float sn, cs;
        sincospif(-(float)j * (1.0f / 2048.0f), &sn, &cs);
        tw[j] = make_float2(cs, sn);
    }
    __syncthreads();

    // accumulators carry 4x (acc2) and 8x (acc3) -> fold 0.25 / 0.125 here
    const float inv_n = 1.0f / ((float)NPIX * (float)NFFT);

    for (int i = tid; i < NFFT; i += NTHF) {
        if (i <= NHALF) A[SWI(i)] = g_acc2[b][i];
        else { float2 v = g_acc2[b][NFFT - i]; A[SWI(i)] = make_float2(v.x, -v.y); }
    }
    __syncthreads();
    // re-zero acc2 for the next launch (all reads completed at the barrier)
    for (int i = tid; i < NSPEC; i += NTHF) g_acc2[b][i] = make_float2(0.f, 0.f);
    fft4096_r8<true>(A, B, tw, tid, NTHF);
    {
        float a2c = alpha[2] * inv_n * 0.25f;
        for (int i = tid; i < NFFT; i += NTHF) phi[513 + i] = A[SWI(i)].x * a2c;
    }
    __syncthreads();

    for (int i = tid; i < NFFT; i += NTHF) {
        if (i <= NHALF) A[SWI(i)] = g_acc3[b][i];
        else { float2 v = g_acc3[b][NFFT - i]; A[SWI(i)] = make_float2(v.x, -v.y); }
    }
    __syncthreads();
    for (int i = tid; i < NSPEC; i += NTHF) g_acc3[b][i] = make_float2(0.f, 0.f);
    fft4096_r8<true>(A, B, tw, tid, NTHF);
    {
        float a3c = alpha[3] * inv_n * 0.125f;
        for (int i = tid; i < NFFT; i += NTHF) phi[513 + NFFT + i] = A[SWI(i)].x * a3c;
    }

    if (tid == 0) phi[0] = alpha[0];
    phi[1 + tid] = alpha[1] * g_first[b][tid] * (1.0f / (float)NPIX);
    g_first[b][tid] = 0.f;              // exclusive read -> safe inline re-zero
    __syncthreads();

    float lsum = 0.f;
    for (int i = tid; i < DOUT; i += NTHF) {
        float v = phi[i];
        float r;
        if (v > 0.f)      r =  sqrtf(v + 1e-12f);
        else if (v < 0.f) r = -sqrtf(-v + 1e-12f);
        else              r = 0.f;
        phi[i] = r;
        lsum += r * r;
    }
    #pragma unroll
    for (int off = 16; off > 0; off >>= 1)
        lsum += __shfl_down_sync(0xffffffffu, lsum, off);
    if ((tid & 31) == 0) red[tid >> 5] = lsum;
    __syncthreads();
    if (tid == 0) {
        float s = 0.f;
        #pragma unroll
        for (int k = 0; k < 16; k++) s += red[k];
        red[16] = 1.0f / sqrtf(s);
    }
    __syncthreads();
    float rn = red[16];
    for (int i = tid; i < DOUT; i += NTHF)
        out[(size_t)b * DOUT + i] = phi[i] * rn;
}

extern "C" void kernel_launch(void* const* d_in, const int* in_sizes, int n_in,
                              void* d_out, int out_size)
{
    const float* x     = (const float*)d_in[0];
    const float* alpha = (const float*)d_in[1];
    const int*   h     = (const int*)d_in[2];
    const int*   sb    = (const int*)d_in[3];
    float*       out   = (float*)d_out;

    const int MAIN_SMEM = (NTW + 6 * APAD) * (int)sizeof(float2);            // 219136
    const int FIN_SMEM  = (NTW + 2 * APAD) * (int)sizeof(float2) + 8712 * 4; // 118816

    cudaFuncSetAttribute(poly_sketch_kernel,
                         cudaFuncAttributeMaxDynamicSharedMemorySize, MAIN_SMEM);
    cudaFuncSetAttribute(finalize_kernel,
                         cudaFuncAttributeMaxDynamicSharedMemorySize, FIN_SMEM);

    poly_sketch_kernel<<<NB * SLOTS, NTHR, MAIN_SMEM>>>(x, h, sb);
    finalize_kernel<<<NB, NTHF, FIN_SMEM>>>(alpha, out);
}

// round 16
// speedup vs baseline: 1.0904x; 1.0095x over previous
#include <cuda_runtime.h>
#include <math.h>

#define NFFT   4096
#define NHALF  2048
#define NSPEC  2049
#define CCH    512
#define NPIX   784
#define NB     8
#define SLOTS  18
#define DOUT   8705
#define NTHR   512
#define NTHF   512

#define NTW    2048     // twiddle table entries (all stage indices < 2048)
#define APAD   4224     // 4096 + 4096/32 padding
#define SWI(i) ((i) + ((i) >> 5))

__device__ float2 g_acc2[NB][NSPEC];    // zero at load; re-zeroed by finalize
__device__ float2 g_acc3[NB][NSPEC];
__device__ float  g_first[NB][CCH];

typedef unsigned long long u64c;   // packed complex: lo = re, hi = im

__device__ __forceinline__ u64c cadd(u64c a, u64c b) {
    u64c r; asm("add.rn.f32x2 %0,%1,%2;" : "=l"(r) : "l"(a), "l"(b)); return r;
}
__device__ __forceinline__ u64c csub(u64c a, u64c b) {
    u64c r; asm("sub.rn.f32x2 %0,%1,%2;" : "=l"(r) : "l"(a), "l"(b)); return r;
}
__device__ __forceinline__ u64c cscale(u64c a, u64c k) {
    u64c r; asm("mul.rn.f32x2 %0,%1,%2;" : "=l"(r) : "l"(a), "l"(k)); return r;
}
__device__ __forceinline__ u64c cmuli(u64c a) {      // i*a = (-im, re)
    float x, y; asm("mov.b64 {%0,%1},%2;" : "=f"(x), "=f"(y) : "l"(a));
    float ny = -y;
    u64c r; asm("mov.b64 %0,{%1,%2};" : "=l"(r) : "f"(ny), "f"(x)); return r;
}
__device__ __forceinline__ u64c cmulmi(u64c a) {     // -i*a = (im, -re)
    float x, y; asm("mov.b64 {%0,%1},%2;" : "=f"(x), "=f"(y) : "l"(a));
    float nx = -x;
    u64c r; asm("mov.b64 %0,{%1,%2};" : "=l"(r) : "f"(y), "f"(nx)); return r;
}
__device__ __forceinline__ float2 unpk(u64c a) {
    float2 r; asm("mov.b64 {%0,%1},%2;" : "=f"(r.x), "=f"(r.y) : "l"(a)); return r;
}
__device__ __forceinline__ u64c pk2(float x, float y) {
    u64c r; asm("mov.b64 %0,{%1,%2};" : "=l"(r) : "f"(x), "f"(y)); return r;
}
__device__ __forceinline__ u64c cc2_const() {        // {CC, CC}
    u64c r; float c = 0.70710678118654752f;
    asm("mov.b64 %0,{%1,%1};" : "=l"(r) : "f"(c)); return r;
}

__device__ __forceinline__ float2 cmul(float2 a, float2 b) {
    return make_float2(a.x * b.x - a.y * b.y, a.x * b.y + a.y * b.x);
}
__device__ __forceinline__ u64c cmulc(u64c z, float wr, float wi) {
    float2 a = unpk(z);
    return pk2(a.x * wr - a.y * wi, a.x * wi + a.y * wr);
}
__device__ __forceinline__ u64c w8m1(u64c z, u64c CC2) {  // z * w8^1
    return cscale(cadd(z, cmulmi(z)), CC2);
}
__device__ __forceinline__ u64c w8m3(u64c z, u64c CC2) {  // z * w8^3
    return cscale(csub(cmulmi(z), z), CC2);
}

// ---------------- DFT16 core: loads 16 strided cells, returns y[16] ----------
__device__ __forceinline__ void bf16_fwd(const float2* __restrict__ src,
                                         int t, u64c* __restrict__ y)
{
    const u64c CC2 = cc2_const();
    const float c1 = 0.92387953251128674f, s1 = 0.38268343236508977f;
    u64c u[4][4];
    #pragma unroll
    for (int j = 0; j < 4; j++) {
        u64c a = *(const u64c*)&src[SWI(t + j * 256)];
        u64c b = *(const u64c*)&src[SWI(t + (j + 4) * 256)];
        u64c c = *(const u64c*)&src[SWI(t + (j + 8) * 256)];
        u64c d = *(const u64c*)&src[SWI(t + (j + 12) * 256)];
        u64c apc = cadd(a, c), amc = csub(a, c);
        u64c bpd = cadd(b, d);
        u64c jb  = cmuli(csub(b, d));
        u[j][0] = cadd(apc, bpd);
        u[j][1] = csub(amc, jb);
        u[j][2] = csub(apc, bpd);
        u[j][3] = cadd(amc, jb);
    }
    u[1][1] = cmulc(u[1][1],  c1, -s1);
    u[1][2] = w8m1(u[1][2], CC2);
    u[1][3] = cmulc(u[1][3],  s1, -c1);
    u[2][1] = w8m1(u[2][1], CC2);
    u[2][2] = cmulmi(u[2][2]);
    u[2][3] = w8m3(u[2][3], CC2);
    u[3][1] = cmulc(u[3][1],  s1, -c1);
    u[3][2] = w8m3(u[3][2], CC2);
    u[3][3] = cmulc(u[3][3], -c1,  s1);
    #pragma unroll
    for (int a = 0; a < 4; a++) {
        u64c p0 = u[0][a], p1 = u[1][a], p2 = u[2][a], p3 = u[3][a];
        u64c q0 = cadd(p0, p2), q1 = csub(p0, p2);
        u64c q2 = cadd(p1, p3);
        u64c jq = cmuli(csub(p1, p3));
        y[a]      = cadd(q0, q2);
        y[a + 4]  = csub(q1, jq);
        y[a + 8]  = csub(q0, q2);
        y[a + 12] = cadd(q1, jq);
    }
}

__device__ __forceinline__ void store16_tw(float2* __restrict__ dst, int o, int s,
                                           const u64c* __restrict__ y,
                                           const float2* W)
{
    dst[SWI(o)] = unpk(y[0]);
    #pragma unroll
    for (int m = 1; m < 16; m++)
        dst[SWI(o + m * s)] = cmul(unpk(y[m]), W[m - 1]);
}
__device__ __forceinline__ void store16_raw(float2* __restrict__ dst, int o, int s,
                                            const u64c* __restrict__ y)
{
    #pragma unroll
    for (int m = 0; m < 16; m++)
        *(u64c*)&dst[SWI(o + m * s)] = y[m];
}

__device__ __forceinline__ void build_W(const float2* __restrict__ tw,
                                        int p, int sh, float2* W)
{
    float2 W1 = tw[p << sh];
    float2 W2 = tw[(2 * p) << sh];
    float2 W4 = tw[(4 * p) << sh];
    float2 W8 = tw[(8 * p) << sh];
    W[0] = W1; W[1] = W2; W[2] = cmul(W1, W2); W[3] = W4;
    W[4] = cmul(W1, W4); W[5] = cmul(W2, W4); W[6] = cmul(W[2], W4);
    W[7] = W8; W[8] = cmul(W1, W8); W[9] = cmul(W2, W8);
    W[10] = cmul(W[2], W8); W[11] = cmul(W4, W8); W[12] = cmul(W[4], W8);
    W[13] = cmul(W[5], W8); W[14] = cmul(W[6], W8);
}

// pair stage: two FFTs (same butterfly index) share one twiddle set
template<bool NOTW>
__device__ __forceinline__ void stage16_pair(const float2* s0, float2* d0,
                                             const float2* s1, float2* d1,
                                             const float2* __restrict__ tw,
                                             int sh, int ls, int t)
{
    int p = t >> ls;
    int q = t & ((1 << ls) - 1);
    int s = 1 << ls;
    int o = q + (p << (ls + 4));
    u64c y[16];
    if (NOTW) {
        bf16_fwd(s0, t, y); store16_raw(d0, o, s, y);
        bf16_fwd(s1, t, y); store16_raw(d1, o, s, y);
    } else {
        float2 W[15];
        build_W(tw, p, sh, W);
        bf16_fwd(s0, t, y); store16_tw(d0, o, s, y, W);
        bf16_fwd(s1, t, y); store16_tw(d1, o, s, y, W);
    }
}

template<bool NOTW>
__device__ __forceinline__ void stage16_one(const float2* s0, float2* d0,
                                            const float2* __restrict__ tw,
                                            int sh, int ls, int t)
{
    int p = t >> ls;
    int q = t & ((1 << ls) - 1);
    int s = 1 << ls;
    int o = q + (p << (ls + 4));
    u64c y[16];
    bf16_fwd(s0, t, y);
    if (NOTW) {
        store16_raw(d0, o, s, y);
    } else {
        float2 W[15];
        build_W(tw, p, sh, W);
        store16_tw(d0, o, s, y, W);
    }
}

// ---------------- generic stage8 (fwd/inv) for the finalize kernel -----------
template<bool INV, bool NOTW>
__device__ __forceinline__ void stage8(const float2* __restrict__ src,
                                       float2* __restrict__ dst,
                                       const float2* __restrict__ tw,
                                       int sh, int ls, int eighth,
                                       int tid, int nt)
{
    const u64c CC2 = cc2_const();
    for (int t = tid; t < eighth; t += nt) {
        int p = t >> ls;
        int q = t & ((1 << ls) - 1);
        u64c x0 = *(const u64c*)&src[SWI(t)];
        u64c x1 = *(const u64c*)&src[SWI(t + eighth)];
        u64c x2 = *(const u64c*)&src[SWI(t + 2 * eighth)];
        u64c x3 = *(const u64c*)&src[SWI(t + 3 * eighth)];
        u64c x4 = *(const u64c*)&src[SWI(t + 4 * eighth)];
        u64c x5 = *(const u64c*)&src[SWI(t + 5 * eighth)];
        u64c x6 = *(const u64c*)&src[SWI(t + 6 * eighth)];
        u64c x7 = *(const u64c*)&src[SWI(t + 7 * eighth)];

        u64c u0 = cadd(x0, x4), u1 = csub(x0, x4);
        u64c u2 = cadd(x2, x6), u3 = csub(x2, x6);
        u64c e0 = cadd(u0, u2), e2 = csub(u0, u2);
        u64c j3 = cmuli(u3);
        u64c e1, e3;
        if (!INV) { e1 = csub(u1, j3); e3 = cadd(u1, j3); }
        else      { e1 = cadd(u1, j3); e3 = csub(u1, j3); }

        u64c v0 = cadd(x1, x5), v1 = csub(x1, x5);
        u64c v2 = cadd(x3, x7), v3 = csub(x3, x7);
        u64c o0 = cadd(v0, v2), o2 = csub(v0, v2);
        u64c k3 = cmuli(v3);
        u64c o1, o3;
        if (!INV) { o1 = csub(v1, k3); o3 = cadd(v1, k3); }
        else      { o1 = cadd(v1, k3); o3 = csub(v1, k3); }

        u64c t1, t2, t3;
        if (!INV) {
            t1 = w8m1(o1, CC2);
            t2 = cmulmi(o2);
            t3 = w8m3(o3, CC2);
        } else {
            t1 = cscale(cadd(o1, cmuli(o1)), CC2);
            t2 = cmuli(o2);
            t3 = cscale(cmuli(cadd(o3, cmuli(o3))), CC2);
        }
        u64c y0 = cadd(e0, o0), y4 = csub(e0, o0);
        u64c y1 = cadd(e1, t1), y5 = csub(e1, t1);
        u64c y2 = cadd(e2, t2), y6 = csub(e2, t2);
        u64c y3 = cadd(e3, t3), y7 = csub(e3, t3);

        int s = 1 << ls;
        int o = q + (p << (ls + 3));
        if (NOTW) {
            *(u64c*)&dst[SWI(o)]       = y0;
            *(u64c*)&dst[SWI(o + s)]   = y1;
            *(u64c*)&dst[SWI(o + 2*s)] = y2;
            *(u64c*)&dst[SWI(o + 3*s)] = y3;
            *(u64c*)&dst[SWI(o + 4*s)] = y4;
            *(u64c*)&dst[SWI(o + 5*s)] = y5;
            *(u64c*)&dst[SWI(o + 6*s)] = y6;
            *(u64c*)&dst[SWI(o + 7*s)] = y7;
        } else {
            float2 w1 = tw[p << sh];
            float2 w2 = tw[(2 * p) << sh];
            float2 w4 = tw[(4 * p) << sh];
            if (INV) { w1.y = -w1.y; w2.y = -w2.y; w4.y = -w4.y; }
            float2 w3 = cmul(w1, w2);
            float2 w5 = cmul(w1, w4);
            float2 w6 = cmul(w2, w4);
            float2 w7 = cmul(w3, w4);
            dst[SWI(o)]       = unpk(y0);
            dst[SWI(o + s)]   = cmul(unpk(y1), w1);
            dst[SWI(o + 2*s)] = cmul(unpk(y2), w2);
            dst[SWI(o + 3*s)] = cmul(unpk(y3), w3);
            dst[SWI(o + 4*s)] = cmul(unpk(y4), w4);
            dst[SWI(o + 5*s)] = cmul(unpk(y5), w5);
            dst[SWI(o + 6*s)] = cmul(unpk(y6), w6);
            dst[SWI(o + 7*s)] = cmul(unpk(y7), w7);
        }
    }
}

template<bool INV>
__device__ void fft4096_r8(float2* A, float2* B, const float2* tw, int tid, int nt)
{
    stage8<INV, false>(A, B, tw, 0, 0, 512, tid, nt); __syncthreads();
    stage8<INV, false>(B, A, tw, 3, 3, 512, tid, nt); __syncthreads();
    stage8<INV, false>(A, B, tw, 6, 6, 512, tid, nt); __syncthreads();
    stage8<INV, true >(B, A, tw, 9, 9, 512, tid, nt); __syncthreads();
}

// Hermitian unpack (2x-scaled): Z = R + i*I with R,I real spectra.
__device__ __forceinline__ void unpack2(float2 Zk, float2 Zm, float2& R, float2& I)
{
    R = make_float2(Zk.x + Zm.x,  Zk.y - Zm.y);
    I = make_float2(Zk.y + Zm.y, -(Zk.x - Zm.x));
}

__global__ void __launch_bounds__(NTHR, 1)
poly_sketch_kernel(const float* __restrict__ x,
                   const int* __restrict__ h_idx,
                   const int* __restrict__ s_bits)
{
    extern __shared__ float2 smem[];
    float2* tw = smem;                  // NTW
    float2* A1 = smem + NTW;            // pixel1 Z buffers
    float2* B1 = A1 + APAD;
    float2* A2 = B1 + APAD;             // pixel2 Z buffers
    float2* B2 = A2 + APAD;
    float2* AD = B2 + APAD;             // packed s2(p1) + i*s2(p2)
    float2* BD = AD + APAD;

    int tid  = threadIdx.x;
    int b    = blockIdx.x / SLOTS;
    int slot = blockIdx.x % SLOTS;

    for (int j = tid; j < NTW; j += NTHR) {
        float sn, cs;
        sincospif(-(float)j * (1.0f / 2048.0f), &sn, &cs);
        tw[j] = make_float2(cs, sn);
    }
    for (int j = tid; j < APAD; j += NTHR) {
        A1[j] = make_float2(0.f, 0.f);
        A2[j] = make_float2(0.f, 0.f);
        AD[j] = make_float2(0.f, 0.f);
    }

    int   h0 = h_idx[tid], h1 = h_idx[CCH + tid], h2 = h_idx[2 * CCH + tid];
    float s0 = (float)(2 * s_bits[tid] - 1);
    float s1 = (float)(2 * s_bits[CCH + tid] - 1);
    float s2 = (float)(2 * s_bits[2 * CCH + tid] - 1);
    __syncthreads();

    float2 a2[4], a3[4], m2, m3;
    #pragma unroll
    for (int i = 0; i < 4; i++) { a2[i] = make_float2(0.f, 0.f); a3[i] = make_float2(0.f, 0.f); }
    m2 = make_float2(0.f, 0.f); m3 = make_float2(0.f, 0.f);
    float xsum = 0.f;

    const float* xrow = x + (size_t)b * NPIX * CCH + tid;
    float x1 = xrow[(size_t)slot * CCH];
    float x2 = (slot + SLOTS < NPIX) ? xrow[(size_t)(slot + SLOTS) * CCH] : 0.f;

    float2 *sA1 = A1, *sB1 = B1, *sA2 = A2, *sB2 = B2, *sAD = AD, *sBD = BD;

    for (int pix = slot; pix < NPIX; pix += 2 * SLOTS) {
        atomicAdd(&sA1[SWI(h0)].x, x1 * s0);
        atomicAdd(&sA1[SWI(h1)].y, x1 * s1);
        atomicAdd(&sA2[SWI(h0)].x, x2 * s0);
        atomicAdd(&sA2[SWI(h1)].y, x2 * s1);
        atomicAdd(&sAD[SWI(h2)].x, x1 * s2);
        atomicAdd(&sAD[SWI(h2)].y, x2 * s2);
        xsum += x1 + x2;
        __syncthreads();

        int n1 = pix + 2 * SLOTS, n2 = pix + 3 * SLOTS;
        float xn1 = (n1 < NPIX) ? xrow[(size_t)n1 * CCH] : 0.f;
        float xn2 = (n2 < NPIX) ? xrow[(size_t)n2 * CCH] : 0.f;

        // phase 1 (ls=0, sh=0)
        if (tid < 256) stage16_pair<false>(sA1, sB1, sAD, sBD, tw, 0, 0, tid);
        else           stage16_one<false>(sA2, sB2, tw, 0, 0, tid - 256);
        __syncthreads();
        // phase 2 (ls=4, sh=4)
        if (tid < 256) stage16_pair<false>(sB1, sA1, sBD, sAD, tw, 4, 4, tid);
        else           stage16_one<false>(sB2, sA2, tw, 4, 4, tid - 256);
        __syncthreads();
        // phase 3 (ls=8, no twiddles)
        if (tid < 256) stage16_pair<true>(sA1, sB1, sAD, sBD, tw, 0, 8, tid);
        else           stage16_one<true>(sA2, sB2, tw, 0, 8, tid - 256);
        __syncthreads();
        // spectra: Z1 in sB1, Z2 in sB2, Dspec in sBD

        #pragma unroll
        for (int jj = 0; jj < 2; jj++) {
            int k  = tid + jj * 512;               // 0..1023
            int km = (NFFT - k) & (NFFT - 1);
            int kb = 2048 - k;
            int kc = 2048 + k;
            float2 Z1k = sB1[SWI(k)],  Z1m = sB1[SWI(km)];
            float2 Z1b = sB1[SWI(kb)], Z1c = sB1[SWI(kc)];
            float2 Z2k = sB2[SWI(k)],  Z2m = sB2[SWI(km)];
            float2 Z2b = sB2[SWI(kb)], Z2c = sB2[SWI(kc)];
            float2 Dk  = sBD[SWI(k)],  Dm  = sBD[SWI(km)];
            float2 Db  = sBD[SWI(kb)], Dc  = sBD[SWI(kc)];

            float2 F0, F1, G0, G1, H0, H1;
            unpack2(Z1k, Z1m, F0, F1);
            unpack2(Z2k, Z2m, G0, G1);
            unpack2(Dk,  Dm,  H0, H1);
            float2 P2 = cmul(F0, F1), P3 = cmul(P2, H0);
            float2 Q2 = cmul(G0, G1), Q3 = cmul(Q2, H1);
            a2[2*jj].x += P2.x + Q2.x; a2[2*jj].y += P2.y + Q2.y;
            a3[2*jj].x += P3.x + Q3.x; a3[2*jj].y += P3.y + Q3.y;

            unpack2(Z1b, Z1c, F0, F1);
            unpack2(Z2b, Z2c, G0, G1);
            unpack2(Db,  Dc,  H0, H1);
            P2 = cmul(F0, F1); P3 = cmul(P2, H0);
            Q2 = cmul(G0, G1); Q3 = cmul(Q2, H1);
            a2[2*jj+1].x += P2.x + Q2.x; a2[2*jj+1].y += P2.y + Q2.y;
            a3[2*jj+1].x += P3.x + Q3.x; a3[2*jj+1].y += P3.y + Q3.y;

            float2 z = make_float2(0.f, 0.f);
            sB1[SWI(k)] = z; sB1[SWI(km)] = z; sB1[SWI(kb)] = z; sB1[SWI(kc)] = z;
            sB2[SWI(k)] = z; sB2[SWI(km)] = z; sB2[SWI(kb)] = z; sB2[SWI(kc)] = z;
            sBD[SWI(k)] = z; sBD[SWI(km)] = z; sBD[SWI(kb)] = z; sBD[SWI(kc)] = z;
        }
        if (tid == 0) {                       // self-paired bin 1024
            float2 Z1k = sB1[SWI(1024)], Z1m = sB1[SWI(3072)];
            float2 Z2k = sB2[SWI(1024)], Z2m = sB2[SWI(3072)];
            float2 Dk  = sBD[SWI(1024)], Dm  = sBD[SWI(3072)];
            float2 F0, F1, G0, G1, H0, H1;
            unpack2(Z1k, Z1m, F0, F1);
            unpack2(Z2k, Z2m, G0, G1);
            unpack2(Dk,  Dm,  H0, H1);
            float2 P2 = cmul(F0, F1), P3 = cmul(P2, H0);
            float2 Q2 = cmul(G0, G1), Q3 = cmul(Q2, H1);
            m2.x += P2.x + Q2.x; m2.y += P2.y + Q2.y;
            m3.x += P3.x + Q3.x; m3.y += P3.y + Q3.y;
            float2 z = make_float2(0.f, 0.f);
            sB1[SWI(1024)] = z; sB1[SWI(3072)] = z;
            sB2[SWI(1024)] = z; sB2[SWI(3072)] = z;
            sBD[SWI(1024)] = z; sBD[SWI(3072)] = z;
        }

        float2* t0;
        t0 = sA1; sA1 = sB1; sB1 = t0;
        t0 = sA2; sA2 = sB2; sB2 = t0;
        t0 = sAD; sAD = sBD; sBD = t0;

        x1 = xn1; x2 = xn2;
        __syncthreads();
    }

    int bins[4] = { tid, 2048 - tid, tid + 512, 1536 - tid };
    #pragma unroll
    for (int i = 0; i < 4; i++) {
        atomicAdd(&g_acc2[b][bins[i]].x, a2[i].x);
        atomicAdd(&g_acc2[b][bins[i]].y, a2[i].y);
        atomicAdd(&g_acc3[b][bins[i]].x, a3[i].x);
        atomicAdd(&g_acc3[b][bins[i]].y, a3[i].y);
    }
    if (tid == 0) {
        atomicAdd(&g_acc2[b][1024].x, m2.x);
        atomicAdd(&g_acc2[b][1024].y, m2.y);
        atomicAdd(&g_acc3[b][1024].x, m3.x);
        atomicAdd(&g_acc3[b][1024].y, m3.y);
    }
    atomicAdd(&g_first[b][tid], xsum);
}

__global__ void __launch_bounds__(NTHF, 1)
finalize_kernel(const float* __restrict__ alpha, float* __restrict__ out)
{
    extern __shared__ float2 smem[];
    float2* tw  = smem;                 // NTW
    float2* A   = smem + NTW;
    float2* B   = A + APAD;
    float*  phi = (float*)(B + APAD);   // 8712 floats
    __shared__ float red[17];

    int tid = threadIdx.x;
    int b   = blockIdx.x;

    for (int j = tid; j < NTW; j += NTHF) {
        float sn, cs;
        sincospif(-(float)j * (1.0f / 2048.0f), &sn, &cs);
        tw[j] = make_float2(cs, sn);
    }
    __syncthreads();

    // accumulators carry 4x (acc2) and 8x (acc3) -> fold 0.25 / 0.125 here
    const float inv_n = 1.0f / ((float)NPIX * (float)NFFT);

    // Pack BOTH Hermitian spectra into one complex array: A = S2 + i*S3.
    // ifft(A).x = ifft(S2) (order-2 result), ifft(A).y = ifft(S3) (order-3).
    for (int i = tid; i < NFFT; i += NTHF) {
        float2 s2v, s3v;
        if (i <= NHALF) { s2v = g_acc2[b][i]; s3v = g_acc3[b][i]; }
        else {
            float2 v2 = g_acc2[b][NFFT - i];
            float2 v3 = g_acc3[b][NFFT - i];
            s2v = make_float2(v2.x, -v2.y);
            s3v = make_float2(v3.x, -v3.y);
        }
        A[SWI(i)] = make_float2(s2v.x - s3v.y, s2v.y + s3v.x);
    }
    __syncthreads();
    // re-zero both accumulators for the next launch (reads done at the barrier)
    for (int i = tid; i < NSPEC; i += NTHF) {
        g_acc2[b][i] = make_float2(0.f, 0.f);
        g_acc3[b][i] = make_float2(0.f, 0.f);
    }
    fft4096_r8<true>(A, B, tw, tid, NTHF);
    {
        float a2c = alpha[2] * inv_n * 0.25f;
        float a3c = alpha[3] * inv_n * 0.125f;
        for (int i = tid; i < NFFT; i += NTHF) {
            float2 v = A[SWI(i)];
            phi[513 + i]        = v.x * a2c;
            phi[513 + NFFT + i] = v.y * a3c;
        }
    }

    if (tid == 0) phi[0] = alpha[0];
    phi[1 + tid] = alpha[1] * g_first[b][tid] * (1.0f / (float)NPIX);
    g_first[b][tid] = 0.f;              // exclusive read -> safe inline re-zero
    __syncthreads();

    float lsum = 0.f;
    for (int i = tid; i < DOUT; i += NTHF) {
        float v = phi[i];
        float r;
        if (v > 0.f)      r =  sqrtf(v + 1e-12f);
        else if (v < 0.f) r = -sqrtf(-v + 1e-12f);
        else              r = 0.f;
        phi[i] = r;
        lsum += r * r;
    }
    #pragma unroll
    for (int off = 16; off > 0; off >>= 1)
        lsum += __shfl_down_sync(0xffffffffu, lsum, off);
    if ((tid & 31) == 0) red[tid >> 5] = lsum;
    __syncthreads();
    if (tid == 0) {
        float s = 0.f;
        #pragma unroll
        for (int k = 0; k < 16; k++) s += red[k];
        red[16] = 1.0f / sqrtf(s);
    }
    __syncthreads();
    float rn = red[16];
    for (int i = tid; i < DOUT; i += NTHF)
        out[(size_t)b * DOUT + i] = phi[i] * rn;
}

extern "C" void kernel_launch(void* const* d_in, const int* in_sizes, int n_in,
                              void* d_out, int out_size)
{
    const float* x     = (const float*)d_in[0];
    const float* alpha = (const float*)d_in[1];
    const int*   h     = (const int*)d_in[2];
    const int*   sb    = (const int*)d_in[3];
    float*       out   = (float*)d_out;

    const int MAIN_SMEM = (NTW + 6 * APAD) * (int)sizeof(float2);            // 219136
    const int FIN_SMEM  = (NTW + 2 * APAD) * (int)sizeof(float2) + 8712 * 4; // 118816

    cudaFuncSetAttribute(poly_sketch_kernel,
                         cudaFuncAttributeMaxDynamicSharedMemorySize, MAIN_SMEM);
    cudaFuncSetAttribute(finalize_kernel,
                         cudaFuncAttributeMaxDynamicSharedMemorySize, FIN_SMEM);

    poly_sketch_kernel<<<NB * SLOTS, NTHR, MAIN_SMEM>>>(x, h, sb);
    finalize_kernel<<<NB, NTHF, FIN_SMEM>>>(alpha, out);
}

// round 17
// speedup vs baseline: 1.0946x; 1.0038x over previous
#include <cuda_runtime.h>
#include <math.h>

#define NFFT   4096
#define NHALF  2048
#define NSPEC  2049
#define CCH    512
#define NPIX   784
#define NB     8
#define SLOTS  18
#define DOUT   8705
#define NTHR   512

#define NTW    2048     // twiddle table entries (all stage indices < 2048)
#define APAD   4224     // 4096 + 4096/32 padding
#define SWI(i) ((i) + ((i) >> 5))

__device__ float2   g_acc2[NB][NSPEC];  // zero at load; re-zeroed by fused finalize
__device__ float2   g_acc3[NB][NSPEC];
__device__ float    g_first[NB][CCH];
__device__ unsigned g_done[NB];         // per-batch arrival counter (reset each launch)

typedef unsigned long long u64c;   // packed complex: lo = re, hi = im

__device__ __forceinline__ u64c cadd(u64c a, u64c b) {
    u64c r; asm("add.rn.f32x2 %0,%1,%2;" : "=l"(r) : "l"(a), "l"(b)); return r;
}
__device__ __forceinline__ u64c csub(u64c a, u64c b) {
    u64c r; asm("sub.rn.f32x2 %0,%1,%2;" : "=l"(r) : "l"(a), "l"(b)); return r;
}
__device__ __forceinline__ u64c cscale(u64c a, u64c k) {
    u64c r; asm("mul.rn.f32x2 %0,%1,%2;" : "=l"(r) : "l"(a), "l"(k)); return r;
}
__device__ __forceinline__ u64c cmuli(u64c a) {      // i*a = (-im, re)
    float x, y; asm("mov.b64 {%0,%1},%2;" : "=f"(x), "=f"(y) : "l"(a));
    float ny = -y;
    u64c r; asm("mov.b64 %0,{%1,%2};" : "=l"(r) : "f"(ny), "f"(x)); return r;
}
__device__ __forceinline__ u64c cmulmi(u64c a) {     // -i*a = (im, -re)
    float x, y; asm("mov.b64 {%0,%1},%2;" : "=f"(x), "=f"(y) : "l"(a));
    float nx = -x;
    u64c r; asm("mov.b64 %0,{%1,%2};" : "=l"(r) : "f"(y), "f"(nx)); return r;
}
__device__ __forceinline__ float2 unpk(u64c a) {
    float2 r; asm("mov.b64 {%0,%1},%2;" : "=f"(r.x), "=f"(r.y) : "l"(a)); return r;
}
__device__ __forceinline__ u64c pk2(float x, float y) {
    u64c r; asm("mov.b64 %0,{%1,%2};" : "=l"(r) : "f"(x), "f"(y)); return r;
}
__device__ __forceinline__ u64c cc2_const() {        // {CC, CC}
    u64c r; float c = 0.70710678118654752f;
    asm("mov.b64 %0,{%1,%1};" : "=l"(r) : "f"(c)); return r;
}

__device__ __forceinline__ float2 cmul(float2 a, float2 b) {
    return make_float2(a.x * b.x - a.y * b.y, a.x * b.y + a.y * b.x);
}
__device__ __forceinline__ u64c cmulc(u64c z, float wr, float wi) {
    float2 a = unpk(z);
    return pk2(a.x * wr - a.y * wi, a.x * wi + a.y * wr);
}
__device__ __forceinline__ u64c w8m1(u64c z, u64c CC2) {  // z * w8^1
    return cscale(cadd(z, cmulmi(z)), CC2);
}
__device__ __forceinline__ u64c w8m3(u64c z, u64c CC2) {  // z * w8^3
    return cscale(csub(cmulmi(z), z), CC2);
}

// ---------------- DFT16 core: loads 16 strided cells, returns y[16] ----------
__device__ __forceinline__ void bf16_fwd(const float2* __restrict__ src,
                                         int t, u64c* __restrict__ y)
{
    const u64c CC2 = cc2_const();
    const float c1 = 0.92387953251128674f, s1 = 0.38268343236508977f;
    u64c u[4][4];
    #pragma unroll
    for (int j = 0; j < 4; j++) {
        u64c a = *(const u64c*)&src[SWI(t + j * 256)];
        u64c b = *(const u64c*)&src[SWI(t + (j + 4) * 256)];
        u64c c = *(const u64c*)&src[SWI(t + (j + 8) * 256)];
        u64c d = *(const u64c*)&src[SWI(t + (j + 12) * 256)];
        u64c apc = cadd(a, c), amc = csub(a, c);
        u64c bpd = cadd(b, d);
        u64c jb  = cmuli(csub(b, d));
        u[j][0] = cadd(apc, bpd);
        u[j][1] = csub(amc, jb);
        u[j][2] = csub(apc, bpd);
        u[j][3] = cadd(amc, jb);
    }
    u[1][1] = cmulc(u[1][1],  c1, -s1);
    u[1][2] = w8m1(u[1][2], CC2);
    u[1][3] = cmulc(u[1][3],  s1, -c1);
    u[2][1] = w8m1(u[2][1], CC2);
    u[2][2] = cmulmi(u[2][2]);
    u[2][3] = w8m3(u[2][3], CC2);
    u[3][1] = cmulc(u[3][1],  s1, -c1);
    u[3][2] = w8m3(u[3][2], CC2);
    u[3][3] = cmulc(u[3][3], -c1,  s1);
    #pragma unroll
    for (int a = 0; a < 4; a++) {
        u64c p0 = u[0][a], p1 = u[1][a], p2 = u[2][a], p3 = u[3][a];
        u64c q0 = cadd(p0, p2), q1 = csub(p0, p2);
        u64c q2 = cadd(p1, p3);
        u64c jq = cmuli(csub(p1, p3));
        y[a]      = cadd(q0, q2);
        y[a + 4]  = csub(q1, jq);
        y[a + 8]  = csub(q0, q2);
        y[a + 12] = cadd(q1, jq);
    }
}

__device__ __forceinline__ void store16_tw(float2* __restrict__ dst, int o, int s,
                                           const u64c* __restrict__ y,
                                           const float2* W)
{
    dst[SWI(o)] = unpk(y[0]);
    #pragma unroll
    for (int m = 1; m < 16; m++)
        dst[SWI(o + m * s)] = cmul(unpk(y[m]), W[m - 1]);
}
__device__ __forceinline__ void store16_raw(float2* __restrict__ dst, int o, int s,
                                            const u64c* __restrict__ y)
{
    #pragma unroll
    for (int m = 0; m < 16; m++)
        *(u64c*)&dst[SWI(o + m * s)] = y[m];
}

__device__ __forceinline__ void build_W(const float2* __restrict__ tw,
                                        int p, int sh, float2* W)
{
    float2 W1 = tw[p << sh];
    float2 W2 = tw[(2 * p) << sh];
    float2 W4 = tw[(4 * p) << sh];
    float2 W8 = tw[(8 * p) << sh];
    W[0] = W1; W[1] = W2; W[2] = cmul(W1, W2); W[3] = W4;
    W[4] = cmul(W1, W4); W[5] = cmul(W2, W4); W[6] = cmul(W[2], W4);
    W[7] = W8; W[8] = cmul(W1, W8); W[9] = cmul(W2, W8);
    W[10] = cmul(W[2], W8); W[11] = cmul(W4, W8); W[12] = cmul(W[4], W8);
    W[13] = cmul(W[5], W8); W[14] = cmul(W[6], W8);
}

// pair stage: two FFTs (same butterfly index) share one twiddle set
template<bool NOTW>
__device__ __forceinline__ void stage16_pair(const float2* s0, float2* d0,
                                             const float2* s1, float2* d1,
                                             const float2* __restrict__ tw,
                                             int sh, int ls, int t)
{
    int p = t >> ls;
    int q = t & ((1 << ls) - 1);
    int s = 1 << ls;
    int o = q + (p << (ls + 4));
    u64c y[16];
    if (NOTW) {
        bf16_fwd(s0, t, y); store16_raw(d0, o, s, y);
        bf16_fwd(s1, t, y); store16_raw(d1, o, s, y);
    } else {
        float2 W[15];
        build_W(tw, p, sh, W);
        bf16_fwd(s0, t, y); store16_tw(d0, o, s, y, W);
        bf16_fwd(s1, t, y); store16_tw(d1, o, s, y, W);
    }
}

template<bool NOTW>
__device__ __forceinline__ void stage16_one(const float2* s0, float2* d0,
                                            const float2* __restrict__ tw,
                                            int sh, int ls, int t)
{
    int p = t >> ls;
    int q = t & ((1 << ls) - 1);
    int s = 1 << ls;
    int o = q + (p << (ls + 4));
    u64c y[16];
    bf16_fwd(s0, t, y);
    if (NOTW) {
        store16_raw(d0, o, s, y);
    } else {
        float2 W[15];
        build_W(tw, p, sh, W);
        store16_tw(d0, o, s, y, W);
    }
}

// ---------------- generic stage8 (inverse path for fused finalize) -----------
template<bool INV, bool NOTW>
__device__ __forceinline__ void stage8(const float2* __restrict__ src,
                                       float2* __restrict__ dst,
                                       const float2* __restrict__ tw,
                                       int sh, int ls, int eighth,
                                       int tid, int nt)
{
    const u64c CC2 = cc2_const();
    for (int t = tid; t < eighth; t += nt) {
        int p = t >> ls;
        int q = t & ((1 << ls) - 1);
        u64c x0 = *(const u64c*)&src[SWI(t)];
        u64c x1 = *(const u64c*)&src[SWI(t + eighth)];
        u64c x2 = *(const u64c*)&src[SWI(t + 2 * eighth)];
        u64c x3 = *(const u64c*)&src[SWI(t + 3 * eighth)];
        u64c x4 = *(const u64c*)&src[SWI(t + 4 * eighth)];
        u64c x5 = *(const u64c*)&src[SWI(t + 5 * eighth)];
        u64c x6 = *(const u64c*)&src[SWI(t + 6 * eighth)];
        u64c x7 = *(const u64c*)&src[SWI(t + 7 * eighth)];

        u64c u0 = cadd(x0, x4), u1 = csub(x0, x4);
        u64c u2 = cadd(x2, x6), u3 = csub(x2, x6);
        u64c e0 = cadd(u0, u2), e2 = csub(u0, u2);
        u64c j3 = cmuli(u3);
        u64c e1, e3;
        if (!INV) { e1 = csub(u1, j3); e3 = cadd(u1, j3); }
        else      { e1 = cadd(u1, j3); e3 = csub(u1, j3); }

        u64c v0 = cadd(x1, x5), v1 = csub(x1, x5);
        u64c v2 = cadd(x3, x7), v3 = csub(x3, x7);
        u64c o0 = cadd(v0, v2), o2 = csub(v0, v2);
        u64c k3 = cmuli(v3);
        u64c o1, o3;
        if (!INV) { o1 = csub(v1, k3); o3 = cadd(v1, k3); }
        else      { o1 = cadd(v1, k3); o3 = csub(v1, k3); }

        u64c t1, t2, t3;
        if (!INV) {
            t1 = w8m1(o1, CC2);
            t2 = cmulmi(o2);
            t3 = w8m3(o3, CC2);
        } else {
            t1 = cscale(cadd(o1, cmuli(o1)), CC2);
            t2 = cmuli(o2);
            t3 = cscale(cmuli(cadd(o3, cmuli(o3))), CC2);
        }
        u64c y0 = cadd(e0, o0), y4 = csub(e0, o0);
        u64c y1 = cadd(e1, t1), y5 = csub(e1, t1);
        u64c y2 = cadd(e2, t2), y6 = csub(e2, t2);
        u64c y3 = cadd(e3, t3), y7 = csub(e3, t3);

        int s = 1 << ls;
        int o = q + (p << (ls + 3));
        if (NOTW) {
            *(u64c*)&dst[SWI(o)]       = y0;
            *(u64c*)&dst[SWI(o + s)]   = y1;
            *(u64c*)&dst[SWI(o + 2*s)] = y2;
            *(u64c*)&dst[SWI(o + 3*s)] = y3;
            *(u64c*)&dst[SWI(o + 4*s)] = y4;
            *(u64c*)&dst[SWI(o + 5*s)] = y5;
            *(u64c*)&dst[SWI(o + 6*s)] = y6;
            *(u64c*)&dst[SWI(o + 7*s)] = y7;
        } else {
            float2 w1 = tw[p << sh];
            float2 w2 = tw[(2 * p) << sh];
            float2 w4 = tw[(4 * p) << sh];
            if (INV) { w1.y = -w1.y; w2.y = -w2.y; w4.y = -w4.y; }
            float2 w3 = cmul(w1, w2);
            float2 w5 = cmul(w1, w4);
            float2 w6 = cmul(w2, w4);
            float2 w7 = cmul(w3, w4);
            dst[SWI(o)]       = unpk(y0);
            dst[SWI(o + s)]   = cmul(unpk(y1), w1);
            dst[SWI(o + 2*s)] = cmul(unpk(y2), w2);
            dst[SWI(o + 3*s)] = cmul(unpk(y3), w3);
            dst[SWI(o + 4*s)] = cmul(unpk(y4), w4);
            dst[SWI(o + 5*s)] = cmul(unpk(y5), w5);
            dst[SWI(o + 6*s)] = cmul(unpk(y6), w6);
            dst[SWI(o + 7*s)] = cmul(unpk(y7), w7);
        }
    }
}

template<bool INV>
__device__ void fft4096_r8(float2* A, float2* B, const float2* tw, int tid, int nt)
{
    stage8<INV, false>(A, B, tw, 0, 0, 512, tid, nt); __syncthreads();
    stage8<INV, false>(B, A, tw, 3, 3, 512, tid, nt); __syncthreads();
    stage8<INV, false>(A, B, tw, 6, 6, 512, tid, nt); __syncthreads();
    stage8<INV, true >(B, A, tw, 9, 9, 512, tid, nt); __syncthreads();
}

// Hermitian unpack (2x-scaled): Z = R + i*I with R,I real spectra.
__device__ __forceinline__ void unpack2(float2 Zk, float2 Zm, float2& R, float2& I)
{
    R = make_float2(Zk.x + Zm.x,  Zk.y - Zm.y);
    I = make_float2(Zk.y + Zm.y, -(Zk.x - Zm.x));
}

__global__ void __launch_bounds__(NTHR, 1)
poly_sketch_kernel(const float* __restrict__ x,
                   const int* __restrict__ h_idx,
                   const int* __restrict__ s_bits,
                   const float* __restrict__ alpha,
                   float* __restrict__ out)
{
    extern __shared__ float2 smem[];
    float2* tw = smem;                  // NTW
    float2* A1 = smem + NTW;            // pixel1 Z buffers
    float2* B1 = A1 + APAD;
    float2* A2 = B1 + APAD;             // pixel2 Z buffers
    float2* B2 = A2 + APAD;
    float2* AD = B2 + APAD;             // packed s2(p1) + i*s2(p2)
    float2* BD = AD + APAD;

    int tid  = threadIdx.x;
    int b    = blockIdx.x / SLOTS;
    int slot = blockIdx.x % SLOTS;

    for (int j = tid; j < NTW; j += NTHR) {
        float sn, cs;
        sincospif(-(float)j * (1.0f / 2048.0f), &sn, &cs);
        tw[j] = make_float2(cs, sn);
    }
    for (int j = tid; j < APAD; j += NTHR) {
        A1[j] = make_float2(0.f, 0.f);
        A2[j] = make_float2(0.f, 0.f);
        AD[j] = make_float2(0.f, 0.f);
    }

    int   h0 = h_idx[tid], h1 = h_idx[CCH + tid], h2 = h_idx[2 * CCH + tid];
    float s0 = (float)(2 * s_bits[tid] - 1);
    float s1 = (float)(2 * s_bits[CCH + tid] - 1);
    float s2 = (float)(2 * s_bits[2 * CCH + tid] - 1);
    __syncthreads();

    float2 a2[4], a3[4], m2, m3;
    #pragma unroll
    for (int i = 0; i < 4; i++) { a2[i] = make_float2(0.f, 0.f); a3[i] = make_float2(0.f, 0.f); }
    m2 = make_float2(0.f, 0.f); m3 = make_float2(0.f, 0.f);
    float xsum = 0.f;

    const float* xrow = x + (size_t)b * NPIX * CCH + tid;
    float x1 = xrow[(size_t)slot * CCH];
    float x2 = (slot + SLOTS < NPIX) ? xrow[(size_t)(slot + SLOTS) * CCH] : 0.f;

    float2 *sA1 = A1, *sB1 = B1, *sA2 = A2, *sB2 = B2, *sAD = AD, *sBD = BD;

    for (int pix = slot; pix < NPIX; pix += 2 * SLOTS) {
        atomicAdd(&sA1[SWI(h0)].x, x1 * s0);
        atomicAdd(&sA1[SWI(h1)].y, x1 * s1);
        atomicAdd(&sA2[SWI(h0)].x, x2 * s0);
        atomicAdd(&sA2[SWI(h1)].y, x2 * s1);
        atomicAdd(&sAD[SWI(h2)].x, x1 * s2);
        atomicAdd(&sAD[SWI(h2)].y, x2 * s2);
        xsum += x1 + x2;
        __syncthreads();

        int n1 = pix + 2 * SLOTS, n2 = pix + 3 * SLOTS;
        float xn1 = (n1 < NPIX) ? xrow[(size_t)n1 * CCH] : 0.f;
        float xn2 = (n2 < NPIX) ? xrow[(size_t)n2 * CCH] : 0.f;

        // phase 1 (ls=0, sh=0)
        if (tid < 256) stage16_pair<false>(sA1, sB1, sAD, sBD, tw, 0, 0, tid);
        else           stage16_one<false>(sA2, sB2, tw, 0, 0, tid - 256);
        __syncthreads();
        // phase 2 (ls=4, sh=4)
        if (tid < 256) stage16_pair<false>(sB1, sA1, sBD, sAD, tw, 4, 4, tid);
        else           stage16_one<false>(sB2, sA2, tw, 4, 4, tid - 256);
        __syncthreads();
        // phase 3 (ls=8, no twiddles)
        if (tid < 256) stage16_pair<true>(sA1, sB1, sAD, sBD, tw, 0, 8, tid);
        else           stage16_one<true>(sA2, sB2, tw, 0, 8, tid - 256);
        __syncthreads();
        // spectra: Z1 in sB1, Z2 in sB2, Dspec in sBD

        #pragma unroll
        for (int jj = 0; jj < 2; jj++) {
            int k  = tid + jj * 512;               // 0..1023
            int km = (NFFT - k) & (NFFT - 1);
            int kb = 2048 - k;
            int kc = 2048 + k;
            float2 Z1k = sB1[SWI(k)],  Z1m = sB1[SWI(km)];
            float2 Z1b = sB1[SWI(kb)], Z1c = sB1[SWI(kc)];
            float2 Z2k = sB2[SWI(k)],  Z2m = sB2[SWI(km)];
            float2 Z2b = sB2[SWI(kb)], Z2c = sB2[SWI(kc)];
            float2 Dk  = sBD[SWI(k)],  Dm  = sBD[SWI(km)];
            float2 Db  = sBD[SWI(kb)], Dc  = sBD[SWI(kc)];

            float2 F0, F1, G0, G1, H0, H1;
            unpack2(Z1k, Z1m, F0, F1);
            unpack2(Z2k, Z2m, G0, G1);
            unpack2(Dk,  Dm,  H0, H1);
            float2 P2 = cmul(F0, F1), P3 = cmul(P2, H0);
            float2 Q2 = cmul(G0, G1), Q3 = cmul(Q2, H1);
            a2[2*jj].x += P2.x + Q2.x; a2[2*jj].y += P2.y + Q2.y;
            a3[2*jj].x += P3.x + Q3.x; a3[2*jj].y += P3.y + Q3.y;

            unpack2(Z1b, Z1c, F0, F1);
            unpack2(Z2b, Z2c, G0, G1);
            unpack2(Db,  Dc,  H0, H1);
            P2 = cmul(F0, F1); P3 = cmul(P2, H0);
            Q2 = cmul(G0, G1); Q3 = cmul(Q2, H1);
            a2[2*jj+1].x += P2.x + Q2.x; a2[2*jj+1].y += P2.y + Q2.y;
            a3[2*jj+1].x += P3.x + Q3.x; a3[2*jj+1].y += P3.y + Q3.y;

            float2 z = make_float2(0.f, 0.f);
            sB1[SWI(k)] = z; sB1[SWI(km)] = z; sB1[SWI(kb)] = z; sB1[SWI(kc)] = z;
            sB2[SWI(k)] = z; sB2[SWI(km)] = z; sB2[SWI(kb)] = z; sB2[SWI(kc)] = z;
            sBD[SWI(k)] = z; sBD[SWI(km)] = z; sBD[SWI(kb)] = z; sBD[SWI(kc)] = z;
        }
        if (tid == 0) {                       // self-paired bin 1024
            float2 Z1k = sB1[SWI(1024)], Z1m = sB1[SWI(3072)];
            float2 Z2k = sB2[SWI(1024)], Z2m = sB2[SWI(3072)];
            float2 Dk  = sBD[SWI(1024)], Dm  = sBD[SWI(3072)];
            float2 F0, F1, G0, G1, H0, H1;
            unpack2(Z1k, Z1m, F0, F1);
            unpack2(Z2k, Z2m, G0, G1);
            unpack2(Dk,  Dm,  H0, H1);
            float2 P2 = cmul(F0, F1), P3 = cmul(P2, H0);
            float2 Q2 = cmul(G0, G1), Q3 = cmul(Q2, H1);
            m2.x += P2.x + Q2.x; m2.y += P2.y + Q2.y;
            m3.x += P3.x + Q3.x; m3.y += P3.y + Q3.y;
            float2 z = make_float2(0.f, 0.f);
            sB1[SWI(1024)] = z; sB1[SWI(3072)] = z;
            sB2[SWI(1024)] = z; sB2[SWI(3072)] = z;
            sBD[SWI(1024)] = z; sBD[SWI(3072)] = z;
        }

        float2* t0;
        t0 = sA1; sA1 = sB1; sB1 = t0;
        t0 = sA2; sA2 = sB2; sB2 = t0;
        t0 = sAD; sAD = sBD; sBD = t0;

        x1 = xn1; x2 = xn2;
        __syncthreads();
    }

    // flush per-CTA accumulators
    int bins[4] = { tid, 2048 - tid, tid + 512, 1536 - tid };
    #pragma unroll
    for (int i = 0; i < 4; i++) {
        atomicAdd(&g_acc2[b][bins[i]].x, a2[i].x);
        atomicAdd(&g_acc2[b][bins[i]].y, a2[i].y);
        atomicAdd(&g_acc3[b][bins[i]].x, a3[i].x);
        atomicAdd(&g_acc3[b][bins[i]].y, a3[i].y);
    }
    if (tid == 0) {
        atomicAdd(&g_acc2[b][1024].x, m2.x);
        atomicAdd(&g_acc2[b][1024].y, m2.y);
        atomicAdd(&g_acc3[b][1024].x, m3.x);
        atomicAdd(&g_acc3[b][1024].y, m3.y);
    }
    atomicAdd(&g_first[b][tid], xsum);

    // ---- last-CTA-per-batch runs the finalize inline -------------------------
    __threadfence();                          // release our flush atomics
    __shared__ unsigned s_rank;
    __shared__ float red[17];
    if (tid == 0) s_rank = atomicAdd(&g_done[b], 1u);
    __syncthreads();
    if (s_rank != SLOTS - 1) return;

    if (tid == 0) g_done[b] = 0;              // reset for next launch/replay
    __threadfence();                          // acquire peers' flushes

    float2* A  = A1;                          // reuse smem
    float2* Bf = B1;
    float*  phi = (float*)A2;                 // 8712 floats (< 2*APAD*8 bytes)

    const float inv_n = 1.0f / ((float)NPIX * (float)NFFT);

    // Pack both Hermitian spectra: A = S2 + i*S3; ifft -> (.x=order2, .y=order3)
    for (int i = tid; i < NFFT; i += NTHR) {
        float2 s2v, s3v;
        if (i <= NHALF) { s2v = g_acc2[b][i]; s3v = g_acc3[b][i]; }
        else {
            float2 v2 = g_acc2[b][NFFT - i];
            float2 v3 = g_acc3[b][NFFT - i];
            s2v = make_float2(v2.x, -v2.y);
            s3v = make_float2(v3.x, -v3.y);
        }
        A[SWI(i)] = make_float2(s2v.x - s3v.y, s2v.y + s3v.x);
    }
    __syncthreads();
    for (int i = tid; i < NSPEC; i += NTHR) {    // re-zero accs (reads done)
        g_acc2[b][i] = make_float2(0.f, 0.f);
        g_acc3[b][i] = make_float2(0.f, 0.f);
    }
    fft4096_r8<true>(A, Bf, tw, tid, NTHR);
    {
        float a2c = alpha[2] * inv_n * 0.25f;
        float a3c = alpha[3] * inv_n * 0.125f;
        for (int i = tid; i < NFFT; i += NTHR) {
            float2 v = A[SWI(i)];
            phi[513 + i]        = v.x * a2c;
            phi[513 + NFFT + i] = v.y * a3c;
        }
    }

    if (tid == 0) phi[0] = alpha[0];
    phi[1 + tid] = alpha[1] * g_first[b][tid] * (1.0f / (float)NPIX);
    g_first[b][tid] = 0.f;
    __syncthreads();

    float lsum = 0.f;
    for (int i = tid; i < DOUT; i += NTHR) {
        float v = phi[i];
        float r;
        if (v > 0.f)      r =  sqrtf(v + 1e-12f);
        else if (v < 0.f) r = -sqrtf(-v + 1e-12f);
        else              r = 0.f;
        phi[i] = r;
        lsum += r * r;
    }
    #pragma unroll
    for (int off = 16; off > 0; off >>= 1)
        lsum += __shfl_down_sync(0xffffffffu, lsum, off);
    if ((tid & 31) == 0) red[tid >> 5] = lsum;
    __syncthreads();
    if (tid == 0) {
        float s = 0.f;
        #pragma unroll
        for (int k = 0; k < 16; k++) s += red[k];
        red[16] = 1.0f / sqrtf(s);
    }
    __syncthreads();
    float rn = red[16];
    for (int i = tid; i < DOUT; i += NTHR)
        out[(size_t)b * DOUT + i] = phi[i] * rn;
}

extern "C" void kernel_launch(void* const* d_in, const int* in_sizes, int n_in,
                              void* d_out, int out_size)
{
    const float* x     = (const float*)d_in[0];
    const float* alpha = (const float*)d_in[1];
    const int*   h     = (const int*)d_in[2];
    const int*   sb    = (const int*)d_in[3];
    float*       out   = (float*)d_out;

    const int MAIN_SMEM = (NTW + 6 * APAD) * (int)sizeof(float2);  // 219136

    cudaFuncSetAttribute(poly_sketch_kernel,
                         cudaFuncAttributeMaxDynamicSharedMemorySize, MAIN_SMEM);

    poly_sketch_kernel<<<NB * SLOTS, NTHR, MAIN_SMEM>>>(x, h, sb, alpha, out);
}